// round 6
// baseline (speedup 1.0000x reference)
#include <cuda_runtime.h>
#include <cstdint>
#include <cstddef>

// B=8, N=1024, C=1024, H=16, D=64, scale = 0.125
#define BB 8
#define NN 1024
#define CC 1024
#define HH 16
#define DD 64
#define SCALE 0.125f
#define FROWS 32

__device__ float g_qkv[(size_t)BB * NN * 3 * CC];   // (B,N,3,H,D)
__device__ float g_ctx[(size_t)BB * NN * CC];       // (B,N,H*D)

__device__ __forceinline__ unsigned f2tf(float f) {
    unsigned u;
    asm("cvt.rna.tf32.f32 %0, %1;" : "=r"(u) : "f"(f));
    return u;
}

__device__ __forceinline__ void mma_tf32(float c[4],
    unsigned a0, unsigned a1, unsigned a2, unsigned a3,
    unsigned b0, unsigned b1)
{
    asm volatile(
        "mma.sync.aligned.m16n8k8.row.col.f32.tf32.tf32.f32 "
        "{%0,%1,%2,%3}, {%4,%5,%6,%7}, {%8,%9}, {%0,%1,%2,%3};\n"
        : "+f"(c[0]), "+f"(c[1]), "+f"(c[2]), "+f"(c[3])
        : "r"(a0), "r"(a1), "r"(a2), "r"(a3), "r"(b0), "r"(b1));
}

// Fragment-packed smem layout notes (m16n8k8, lane = g*4+t, g=l>>2, t=l&3):
//  A element (mrow 0..15 within m-tile, kk 0..7 within slab):
//    lane = (mrow&7)*4 + (kk&3), reg = (mrow>>3) + 2*(kk>>2)   -> uint4/lane
//  B element (kk 0..7, ncol 0..7 within n-tile):
//    lane = ncol*4 + (kk&3),     reg = kk>>2                    -> uint2/lane

// ---------------------------------------------------------------------------
// TF32 TC SGEMM + bias. 128x128 tile, BK=16, 256 thr (8 warps, 4x2),
// warp tile 32x64. Fragment-packed smem + 2-stage double buffer.
// ---------------------------------------------------------------------------
__global__ __launch_bounds__(256, 2) void sgemm_bias_tc(
    const float* __restrict__ A, const float* __restrict__ Bm,
    const float* __restrict__ bias, float* __restrict__ C,
    int M, int N, int K)
{
    __shared__ uint4 AsF[2][2][8][32];    // [stage][slab][m_tile][lane]
    __shared__ uint2 BsF[2][2][16][32];   // [stage][slab][n_tile][lane]

    const int tid  = threadIdx.x;
    const int brow = blockIdx.y * 128;
    const int bcol = blockIdx.x * 128;
    const int w  = tid >> 5, l = tid & 31;
    const int wr = w >> 1, wc = w & 1;
    const int g  = l >> 2, t = l & 3;

    const int ar  = tid >> 1;         // A row 0..127
    const int ac4 = (tid & 1) * 2;    // A float4-col base

    float4 a_r[2], b_r[2];
    auto ldg_tiles = [&](int k0) {
#pragma unroll
        for (int j = 0; j < 2; j++)
            a_r[j] = *reinterpret_cast<const float4*>(
                &A[(size_t)(brow + ar) * K + k0 + (ac4 + j) * 4]);
#pragma unroll
        for (int j = 0; j < 2; j++) {
            const int idx = tid * 2 + j;
            const int r = idx >> 5, c4 = idx & 31;
            b_r[j] = *reinterpret_cast<const float4*>(
                &Bm[(size_t)(k0 + r) * N + bcol + c4 * 4]);
        }
    };
    auto sts_tiles = [&](int st) {
        const int mrow = ar & 15, m_tile = ar >> 4;
        const int lane0 = (mrow & 7) * 4;
        const int rh = mrow >> 3;
#pragma unroll
        for (int j = 0; j < 2; j++) {
            const int c4 = ac4 + j;
            const int slab = c4 >> 1;
            const int reg = rh + 2 * (c4 & 1);
            unsigned* dst = reinterpret_cast<unsigned*>(&AsF[st][slab][m_tile][0]);
            dst[(lane0 + 0) * 4 + reg] = f2tf(a_r[j].x);
            dst[(lane0 + 1) * 4 + reg] = f2tf(a_r[j].y);
            dst[(lane0 + 2) * 4 + reg] = f2tf(a_r[j].z);
            dst[(lane0 + 3) * 4 + reg] = f2tf(a_r[j].w);
        }
#pragma unroll
        for (int j = 0; j < 2; j++) {
            const int idx = tid * 2 + j;
            const int r = idx >> 5, c4 = idx & 31;
            const int slab = r >> 3, kk = r & 7;
            const int reg = kk >> 2;
            const int base = (c4 & 1) * 16 + (kk & 3);
            unsigned* dst = reinterpret_cast<unsigned*>(&BsF[st][slab][c4 >> 1][0]);
            dst[(base + 0)  * 2 + reg] = f2tf(b_r[j].x);
            dst[(base + 4)  * 2 + reg] = f2tf(b_r[j].y);
            dst[(base + 8)  * 2 + reg] = f2tf(b_r[j].z);
            dst[(base + 12) * 2 + reg] = f2tf(b_r[j].w);
        }
    };

    float acc[2][8][4];
#pragma unroll
    for (int i = 0; i < 2; i++)
#pragma unroll
        for (int j = 0; j < 8; j++)
#pragma unroll
            for (int r = 0; r < 4; r++) acc[i][j][r] = 0.0f;

    const int nIter = K >> 4;
    ldg_tiles(0);
    sts_tiles(0);
    __syncthreads();
    for (int it = 0; it < nIter; it++) {
        if (it + 1 < nIter) ldg_tiles((it + 1) << 4);
        const int st = it & 1;
#pragma unroll
        for (int s = 0; s < 2; s++) {
            uint4 a0 = AsF[st][s][wr * 2 + 0][l];
            uint4 a1 = AsF[st][s][wr * 2 + 1][l];
            uint2 b[8];
#pragma unroll
            for (int j = 0; j < 8; j++) b[j] = BsF[st][s][wc * 8 + j][l];
#pragma unroll
            for (int j = 0; j < 8; j++) {
                mma_tf32(acc[0][j], a0.x, a0.y, a0.z, a0.w, b[j].x, b[j].y);
                mma_tf32(acc[1][j], a1.x, a1.y, a1.z, a1.w, b[j].x, b[j].y);
            }
        }
        if (it + 1 < nIter) { sts_tiles((it + 1) & 1); __syncthreads(); }
    }

#pragma unroll
    for (int j = 0; j < 8; j++) {
        const int col = bcol + wc * 64 + j * 8 + t * 2;
        const float b0 = bias[col], b1 = bias[col + 1];
#pragma unroll
        for (int i = 0; i < 2; i++) {
            const int r0 = brow + wr * 32 + i * 16;
            float2 o0 = {acc[i][j][0] + b0, acc[i][j][1] + b1};
            float2 o1 = {acc[i][j][2] + b0, acc[i][j][3] + b1};
            *reinterpret_cast<float2*>(&C[(size_t)(r0 + g) * N + col]) = o0;
            *reinterpret_cast<float2*>(&C[(size_t)(r0 + g + 8) * N + col]) = o1;
        }
    }
}

// ---------------------------------------------------------------------------
// Fused QK^T + softmax (single attn write). 32 rows x 1024 keys per block,
// 512 threads. Fragment-packed Q/K smem, double-buffered K chunks.
// Dyn smem: QF [8][2][32] uint4 (8KB) | KF [2][8][16][32] uint2 (64KB)
// ---------------------------------------------------------------------------
__global__ __launch_bounds__(512) void qk_softmax_fused(
    const float* __restrict__ qkv, float* __restrict__ attn)
{
    extern __shared__ unsigned dyn[];
    uint4* QF = reinterpret_cast<uint4*>(dyn);            // [slab8][mt2][lane]
    uint2* KF = reinterpret_cast<uint2*>(dyn + 2048);     // [st2][slab8][nt16][lane]
    __shared__ float redM[32 * 9];
    __shared__ float redS[32 * 9];

    const int bh = blockIdx.y;
    const int b  = bh >> 4;
    const int h  = bh & 15;
    const int n0 = blockIdx.x * FROWS;

    const int tid = threadIdx.x;
    const int w = tid >> 5, l = tid & 31;
    const int g = l >> 2, t = l & 3;
    const int wr = w >> 3, wc = w & 7;

    const float* qbase = qkv + (size_t)b * NN * 3 * CC + h * DD;
    const float* kbase = qbase + CC;

    // Q fill (fragment-packed, pre-scaled)
    {
        const int r  = tid >> 4;
        const int c4 = tid & 15;
        float4 v = *reinterpret_cast<const float4*>(
            qbase + (size_t)(n0 + r) * (3 * CC) + c4 * 4);
        const int slab = c4 >> 1;
        const int mrow = r & 15, m_tile = r >> 4;
        const int reg = (mrow >> 3) + 2 * (c4 & 1);
        const int lane0 = (mrow & 7) * 4;
        unsigned* dst = reinterpret_cast<unsigned*>(&QF[(slab * 2 + m_tile) * 32]);
        dst[(lane0 + 0) * 4 + reg] = f2tf(v.x * SCALE);
        dst[(lane0 + 1) * 4 + reg] = f2tf(v.y * SCALE);
        dst[(lane0 + 2) * 4 + reg] = f2tf(v.z * SCALE);
        dst[(lane0 + 3) * 4 + reg] = f2tf(v.w * SCALE);
    }

    float4 kpre[4];
    auto ldg_k = [&](int m0) {
#pragma unroll
        for (int j = 0; j < 4; j++) {
            const int idx = tid + 512 * j;
            const int m = idx >> 4, c4 = idx & 15;
            kpre[j] = *reinterpret_cast<const float4*>(
                kbase + (size_t)(m0 + m) * (3 * CC) + c4 * 4);
        }
    };
    auto sts_k = [&](int st) {
#pragma unroll
        for (int j = 0; j < 4; j++) {
            const int idx = tid + 512 * j;
            const int m = idx >> 4, c4 = idx & 15;
            const int slab = c4 >> 1, reg = c4 & 1;
            const int lane0 = (m & 7) * 4;
            unsigned* dst = reinterpret_cast<unsigned*>(
                &KF[((st * 8 + slab) * 16 + (m >> 3)) * 32]);
            dst[(lane0 + 0) * 2 + reg] = f2tf(kpre[j].x);
            dst[(lane0 + 1) * 2 + reg] = f2tf(kpre[j].y);
            dst[(lane0 + 2) * 2 + reg] = f2tf(kpre[j].z);
            dst[(lane0 + 3) * 2 + reg] = f2tf(kpre[j].w);
        }
    };

    float acc[8][2][4];
#pragma unroll
    for (int c = 0; c < 8; c++)
#pragma unroll
        for (int jn = 0; jn < 2; jn++)
#pragma unroll
            for (int r = 0; r < 4; r++) acc[c][jn][r] = 0.0f;

    const int row0 = wr * 16 + g;
    const int row1 = row0 + 8;

    ldg_k(0);
    sts_k(0);
    __syncthreads();
#pragma unroll
    for (int c = 0; c < 8; c++) {
        if (c < 7) ldg_k((c + 1) * 128);
        const int st = c & 1;
#pragma unroll
        for (int s = 0; s < 8; s++) {
            uint4 a = QF[(s * 2 + wr) * 32 + l];
#pragma unroll
            for (int jn = 0; jn < 2; jn++) {
                uint2 bb = KF[((st * 8 + s) * 16 + wc * 2 + jn) * 32 + l];
                mma_tf32(acc[c][jn], a.x, a.y, a.z, a.w, bb.x, bb.y);
            }
        }
        if (c < 7) { sts_k((c + 1) & 1); __syncthreads(); }
    }

    // ---- softmax over full 1024-wide rows ----
    float mx0 = -3.402823466e+38f, mx1 = -3.402823466e+38f;
#pragma unroll
    for (int c = 0; c < 8; c++)
#pragma unroll
        for (int jn = 0; jn < 2; jn++) {
            mx0 = fmaxf(mx0, fmaxf(acc[c][jn][0], acc[c][jn][1]));
            mx1 = fmaxf(mx1, fmaxf(acc[c][jn][2], acc[c][jn][3]));
        }
#pragma unroll
    for (int o = 1; o <= 2; o <<= 1) {
        mx0 = fmaxf(mx0, __shfl_xor_sync(0xffffffffu, mx0, o));
        mx1 = fmaxf(mx1, __shfl_xor_sync(0xffffffffu, mx1, o));
    }
    if (t == 0) {
        redM[row0 * 9 + wc] = mx0;
        redM[row1 * 9 + wc] = mx1;
    }
    __syncthreads();
    mx0 = redM[row0 * 9];
    mx1 = redM[row1 * 9];
#pragma unroll
    for (int k = 1; k < 8; k++) {
        mx0 = fmaxf(mx0, redM[row0 * 9 + k]);
        mx1 = fmaxf(mx1, redM[row1 * 9 + k]);
    }

    float s0 = 0.0f, s1 = 0.0f;
#pragma unroll
    for (int c = 0; c < 8; c++)
#pragma unroll
        for (int jn = 0; jn < 2; jn++) {
            acc[c][jn][0] = __expf(acc[c][jn][0] - mx0);
            acc[c][jn][1] = __expf(acc[c][jn][1] - mx0);
            acc[c][jn][2] = __expf(acc[c][jn][2] - mx1);
            acc[c][jn][3] = __expf(acc[c][jn][3] - mx1);
            s0 += acc[c][jn][0] + acc[c][jn][1];
            s1 += acc[c][jn][2] + acc[c][jn][3];
        }
#pragma unroll
    for (int o = 1; o <= 2; o <<= 1) {
        s0 += __shfl_xor_sync(0xffffffffu, s0, o);
        s1 += __shfl_xor_sync(0xffffffffu, s1, o);
    }
    if (t == 0) {
        redS[row0 * 9 + wc] = s0;
        redS[row1 * 9 + wc] = s1;
    }
    __syncthreads();
    s0 = redS[row0 * 9];
    s1 = redS[row1 * 9];
#pragma unroll
    for (int k = 1; k < 8; k++) {
        s0 += redS[row0 * 9 + k];
        s1 += redS[row1 * 9 + k];
    }
    const float inv0 = 1.0f / s0;
    const float inv1 = 1.0f / s1;

    float* arow0 = attn + ((size_t)bh * NN + n0 + row0) * NN;
    float* arow1 = attn + ((size_t)bh * NN + n0 + row1) * NN;
#pragma unroll
    for (int c = 0; c < 8; c++)
#pragma unroll
        for (int jn = 0; jn < 2; jn++) {
            const int col = c * 128 + wc * 16 + jn * 8 + 2 * t;
            float2 o0 = {acc[c][jn][0] * inv0, acc[c][jn][1] * inv0};
            float2 o1 = {acc[c][jn][2] * inv1, acc[c][jn][3] * inv1};
            *reinterpret_cast<float2*>(&arow0[col]) = o0;
            *reinterpret_cast<float2*>(&arow1[col]) = o1;
        }
}

// ---------------------------------------------------------------------------
// PV: ctx = attn @ V. 128 rows x 64 cols, BK=32, 256 thr, warp tile 32x32.
// Fragment-packed smem + 2-stage double buffer.
// Dyn smem: PF [2][4][8][32] uint4 (32KB) | VF [2][4][8][32] uint2 (16KB)
// ---------------------------------------------------------------------------
__global__ __launch_bounds__(256, 2) void av_ctx_tc(
    const float* __restrict__ attn, const float* __restrict__ qkv,
    float* __restrict__ ctx)
{
    extern __shared__ unsigned dyn[];
    uint4* PF = reinterpret_cast<uint4*>(dyn);            // [st][slab4][mt8][lane]
    uint2* VF = reinterpret_cast<uint2*>(dyn + 8192);     // [st][slab4][nt8][lane]

    const int bh = blockIdx.y;
    const int b  = bh >> 4;
    const int h  = bh & 15;
    const int n0 = blockIdx.x * 128;

    const float* vbase = qkv + (size_t)b * NN * 3 * CC + 2 * CC + h * DD;
    const float* arow  = attn + ((size_t)bh * NN + n0) * NN;

    const int tid = threadIdx.x;
    const int w  = tid >> 5, l = tid & 31;
    const int wr = w >> 1, wc = w & 1;
    const int g  = l >> 2, t = l & 3;

    float4 p_r[4], v_r[2];
    auto ldg_tiles = [&](int k0) {
#pragma unroll
        for (int j = 0; j < 4; j++) {
            const int idx = tid * 4 + j;
            const int r = idx >> 3, c4 = idx & 7;
            p_r[j] = *reinterpret_cast<const float4*>(
                arow + (size_t)r * NN + k0 + c4 * 4);
        }
#pragma unroll
        for (int j = 0; j < 2; j++) {
            const int idx = tid * 2 + j;
            const int r = idx >> 4, c4 = idx & 15;
            v_r[j] = *reinterpret_cast<const float4*>(
                vbase + (size_t)(k0 + r) * (3 * CC) + c4 * 4);
        }
    };
    auto sts_tiles = [&](int st) {
#pragma unroll
        for (int j = 0; j < 4; j++) {
            const int idx = tid * 4 + j;
            const int r = idx >> 3, c4 = idx & 7;
            const int slab = c4 >> 1;
            const int mrow = r & 15, m_tile = r >> 4;
            const int reg = (mrow >> 3) + 2 * (c4 & 1);
            const int lane0 = (mrow & 7) * 4;
            unsigned* dst = reinterpret_cast<unsigned*>(
                &PF[((st * 4 + slab) * 8 + m_tile) * 32]);
            dst[(lane0 + 0) * 4 + reg] = f2tf(p_r[j].x);
            dst[(lane0 + 1) * 4 + reg] = f2tf(p_r[j].y);
            dst[(lane0 + 2) * 4 + reg] = f2tf(p_r[j].z);
            dst[(lane0 + 3) * 4 + reg] = f2tf(p_r[j].w);
        }
#pragma unroll
        for (int j = 0; j < 2; j++) {
            const int idx = tid * 2 + j;
            const int r = idx >> 4, c4 = idx & 15;
            const int slab = r >> 3, kk = r & 7;
            const int reg = kk >> 2;
            const int base = (c4 & 1) * 16 + (kk & 3);
            unsigned* dst = reinterpret_cast<unsigned*>(
                &VF[((st * 4 + slab) * 8 + (c4 >> 1)) * 32]);
            dst[(base + 0)  * 2 + reg] = f2tf(v_r[j].x);
            dst[(base + 4)  * 2 + reg] = f2tf(v_r[j].y);
            dst[(base + 8)  * 2 + reg] = f2tf(v_r[j].z);
            dst[(base + 12) * 2 + reg] = f2tf(v_r[j].w);
        }
    };

    float acc[2][4][4];
#pragma unroll
    for (int i = 0; i < 2; i++)
#pragma unroll
        for (int j = 0; j < 4; j++)
#pragma unroll
            for (int r = 0; r < 4; r++) acc[i][j][r] = 0.0f;

    const int nIter = NN / 32;
    ldg_tiles(0);
    sts_tiles(0);
    __syncthreads();
    for (int it = 0; it < nIter; it++) {
        if (it + 1 < nIter) ldg_tiles((it + 1) * 32);
        const int st = it & 1;
#pragma unroll
        for (int s = 0; s < 4; s++) {
            uint4 a0 = PF[((st * 4 + s) * 8 + wr * 2 + 0) * 32 + l];
            uint4 a1 = PF[((st * 4 + s) * 8 + wr * 2 + 1) * 32 + l];
            uint2 bb[4];
#pragma unroll
            for (int j = 0; j < 4; j++)
                bb[j] = VF[((st * 4 + s) * 8 + wc * 4 + j) * 32 + l];
#pragma unroll
            for (int j = 0; j < 4; j++) {
                mma_tf32(acc[0][j], a0.x, a0.y, a0.z, a0.w, bb[j].x, bb[j].y);
                mma_tf32(acc[1][j], a1.x, a1.y, a1.z, a1.w, bb[j].x, bb[j].y);
            }
        }
        if (it + 1 < nIter) { sts_tiles((it + 1) & 1); __syncthreads(); }
    }

#pragma unroll
    for (int j = 0; j < 4; j++) {
        const int col = h * DD + wc * 32 + j * 8 + t * 2;
#pragma unroll
        for (int i = 0; i < 2; i++) {
            const int r0 = n0 + wr * 32 + i * 16;
            float2 o0 = {acc[i][j][0], acc[i][j][1]};
            float2 o1 = {acc[i][j][2], acc[i][j][3]};
            *reinterpret_cast<float2*>(
                &ctx[((size_t)b * NN + r0 + g) * CC + col]) = o0;
            *reinterpret_cast<float2*>(
                &ctx[((size_t)b * NN + r0 + g + 8) * CC + col]) = o1;
        }
    }
}

// ---------------------------------------------------------------------------
extern "C" void kernel_launch(void* const* d_in, const int* in_sizes, int n_in,
                              void* d_out, int out_size)
{
    (void)in_sizes; (void)n_in; (void)out_size;
    const float* x      = (const float*)d_in[0];
    const float* w_qkv  = (const float*)d_in[1];
    const float* b_qkv  = (const float*)d_in[2];
    const float* w_proj = (const float*)d_in[3];
    const float* b_proj = (const float*)d_in[4];

    float* out  = (float*)d_out;
    float* attn = out + (size_t)BB * NN * CC;

    float* qkvp = nullptr;
    float* ctxp = nullptr;
    cudaGetSymbolAddress((void**)&qkvp, g_qkv);
    cudaGetSymbolAddress((void**)&ctxp, g_ctx);

    const int qk_smem = 8192 + 65536;   // QF + KF
    const int av_smem = 32768 + 16384;  // PF + VF
    cudaFuncSetAttribute(qk_softmax_fused,
        cudaFuncAttributeMaxDynamicSharedMemorySize, qk_smem);
    cudaFuncSetAttribute(av_ctx_tc,
        cudaFuncAttributeMaxDynamicSharedMemorySize, av_smem);

    // 1) QKV projection
    sgemm_bias_tc<<<dim3(3 * CC / 128, BB * NN / 128), 256>>>(
        x, w_qkv, b_qkv, qkvp, BB * NN, 3 * CC, CC);

    // 2) Fused QK^T + softmax -> attn (single write)
    qk_softmax_fused<<<dim3(NN / FROWS, BB * HH), 512, qk_smem>>>(qkvp, attn);

    // 3) attn @ V
    av_ctx_tc<<<dim3(NN / 128, BB * HH), 256, av_smem>>>(attn, qkvp, ctxp);

    // 4) Output projection
    sgemm_bias_tc<<<dim3(CC / 128, BB * NN / 128), 256>>>(
        ctxp, w_proj, b_proj, out, BB * NN, CC, CC);
}

// round 7
// speedup vs baseline: 2.4856x; 2.4856x over previous
#include <cuda_runtime.h>
#include <cuda_fp16.h>
#include <cstdint>
#include <cstddef>

// B=8, N=1024, C=1024, H=16, D=64, scale = 0.125
#define BB 8
#define NN 1024
#define CC 1024
#define HH 16
#define DD 64
#define SCALE 0.125f
#define FROWS 32

__device__ __half g_xh[(size_t)BB * NN * CC];          // x in fp16
__device__ __half g_qkvh[(size_t)BB * NN * 3 * CC];    // qkv fp16 (B,N,3,H,D)
__device__ __half g_ctxh[(size_t)BB * NN * CC];        // ctx fp16 (B,N,H*D)
__device__ __half g_wqkvT[(size_t)3 * CC * CC];        // [n][k] fp16
__device__ __half g_wprojT[(size_t)CC * CC];           // [n][k] fp16
__device__ __half g_vt[(size_t)BB * HH * DD * NN];     // [bh][d][m] fp16

__device__ __forceinline__ unsigned pack_h2(float a, float b) {
    __half2 h = __floats2half2_rn(a, b);
    return *reinterpret_cast<unsigned*>(&h);
}

__device__ __forceinline__ void mma_f16(float c[4],
    unsigned a0, unsigned a1, unsigned a2, unsigned a3,
    unsigned b0, unsigned b1)
{
    asm volatile(
        "mma.sync.aligned.m16n8k16.row.col.f32.f16.f16.f32 "
        "{%0,%1,%2,%3}, {%4,%5,%6,%7}, {%8,%9}, {%0,%1,%2,%3};\n"
        : "+f"(c[0]), "+f"(c[1]), "+f"(c[2]), "+f"(c[3])
        : "r"(a0), "r"(a1), "r"(a2), "r"(a3), "r"(b0), "r"(b1));
}

// ---------------------------------------------------------------------------
// fp32 -> fp16 bulk convert (8 elems/thread)
// ---------------------------------------------------------------------------
__global__ void cvt_f32_h(const float* __restrict__ in,
                          __half* __restrict__ out, int n8)
{
    int i = blockIdx.x * blockDim.x + threadIdx.x;
    if (i >= n8) return;
    const float4* p = reinterpret_cast<const float4*>(in) + (size_t)i * 2;
    float4 v0 = p[0], v1 = p[1];
    uint4 u;
    u.x = pack_h2(v0.x, v0.y);
    u.y = pack_h2(v0.z, v0.w);
    u.z = pack_h2(v1.x, v1.y);
    u.w = pack_h2(v1.z, v1.w);
    reinterpret_cast<uint4*>(out)[i] = u;
}

// ---------------------------------------------------------------------------
// W [K][N] fp32 -> WT [N][K] fp16 (tiled transpose)
// ---------------------------------------------------------------------------
__global__ void transpose_w_h(const float* __restrict__ W,
                              __half* __restrict__ WT, int K, int N)
{
    __shared__ float tile[32][33];
    const int k0 = blockIdx.x * 32, n0 = blockIdx.y * 32;
    for (int i = threadIdx.y; i < 32; i += 8)
        tile[i][threadIdx.x] = W[(size_t)(k0 + i) * N + n0 + threadIdx.x];
    __syncthreads();
    for (int i = threadIdx.y; i < 32; i += 8)
        WT[(size_t)(n0 + i) * K + k0 + threadIdx.x] =
            __float2half_rn(tile[threadIdx.x][i]);
}

// ---------------------------------------------------------------------------
// V slice of g_qkvh (B,N,3,H,D) -> g_vt [bh][d][m] fp16
// ---------------------------------------------------------------------------
__global__ __launch_bounds__(256) void transpose_v_h(
    const __half* __restrict__ qkvh, __half* __restrict__ vt)
{
    __shared__ __half tile[128][72];
    const int bh = blockIdx.y;
    const int b = bh >> 4, h = bh & 15;
    const int m0 = blockIdx.x * 128;
    const __half* vb = qkvh + (size_t)b * NN * 3 * CC + 2 * CC + h * DD;

#pragma unroll
    for (int it = 0; it < 4; it++) {
        const int idx = threadIdx.x + 256 * it;
        const int m = idx >> 3, c8 = idx & 7;
        uint4 v = *reinterpret_cast<const uint4*>(
            vb + (size_t)(m0 + m) * 3 * CC + c8 * 8);
        *reinterpret_cast<uint4*>(&tile[m][c8 * 8]) = v;
    }
    __syncthreads();
    __half* ob = vt + (size_t)bh * DD * NN + m0;
#pragma unroll
    for (int it = 0; it < 4; it++) {
        const int idx = threadIdx.x + 256 * it;
        const int d = idx >> 4, mc = idx & 15;
        __half hbuf[8];
#pragma unroll
        for (int j = 0; j < 8; j++) hbuf[j] = tile[mc * 8 + j][d];
        *reinterpret_cast<uint4*>(ob + (size_t)d * NN + mc * 8) =
            *reinterpret_cast<uint4*>(hbuf);
    }
}

// ---------------------------------------------------------------------------
// fp16 TC GEMM + bias: C[M,N] = Ah[M,K] @ BT[N,K]^T + bias
// 128x128 tile, BK=32, 256 thr (8 warps 4x2), warp tile 32x64.
// out_half: 1 -> fp16 C, 0 -> fp32 C.
// ---------------------------------------------------------------------------
__global__ __launch_bounds__(256) void gemm_h(
    const __half* __restrict__ Ah, const __half* __restrict__ BT,
    const float* __restrict__ bias, void* __restrict__ Cout,
    int M, int N, int K, int out_half)
{
    __shared__ __align__(16) __half As[2][128][40];
    __shared__ __align__(16) __half Bs[2][128][40];

    const int tid  = threadIdx.x;
    const int brow = blockIdx.y * 128;
    const int bcol = blockIdx.x * 128;
    const int w = tid >> 5, l = tid & 31;
    const int wr = w >> 1, wc = w & 1;
    const int g = l >> 2, t = l & 3;

    uint4 a_r[2], b_r[2];
    auto ldg_tiles = [&](int k0) {
#pragma unroll
        for (int j = 0; j < 2; j++) {
            const int idx = tid * 2 + j;
            const int row = idx >> 2, c8 = idx & 3;
            a_r[j] = *reinterpret_cast<const uint4*>(
                Ah + (size_t)(brow + row) * K + k0 + c8 * 8);
            b_r[j] = *reinterpret_cast<const uint4*>(
                BT + (size_t)(bcol + row) * K + k0 + c8 * 8);
        }
    };
    auto sts_tiles = [&](int st) {
#pragma unroll
        for (int j = 0; j < 2; j++) {
            const int idx = tid * 2 + j;
            const int row = idx >> 2, c8 = idx & 3;
            *reinterpret_cast<uint4*>(&As[st][row][c8 * 8]) = a_r[j];
            *reinterpret_cast<uint4*>(&Bs[st][row][c8 * 8]) = b_r[j];
        }
    };

    float acc[2][8][4];
#pragma unroll
    for (int i = 0; i < 2; i++)
#pragma unroll
        for (int j = 0; j < 8; j++)
#pragma unroll
            for (int r = 0; r < 4; r++) acc[i][j][r] = 0.0f;

    const int nIter = K >> 5;
    ldg_tiles(0);
    sts_tiles(0);
    __syncthreads();
    for (int it = 0; it < nIter; it++) {
        if (it + 1 < nIter) ldg_tiles((it + 1) << 5);
        const int st = it & 1;
#pragma unroll
        for (int ss = 0; ss < 2; ss++) {
            const int kk = ss * 16;
            unsigned a[2][4];
#pragma unroll
            for (int i = 0; i < 2; i++) {
                const int m = wr * 32 + i * 16;
                a[i][0] = *reinterpret_cast<unsigned*>(&As[st][m + g][kk + 2 * t]);
                a[i][1] = *reinterpret_cast<unsigned*>(&As[st][m + g + 8][kk + 2 * t]);
                a[i][2] = *reinterpret_cast<unsigned*>(&As[st][m + g][kk + 2 * t + 8]);
                a[i][3] = *reinterpret_cast<unsigned*>(&As[st][m + g + 8][kk + 2 * t + 8]);
            }
            unsigned b[8][2];
#pragma unroll
            for (int j = 0; j < 8; j++) {
                const int n0 = wc * 64 + j * 8;
                b[j][0] = *reinterpret_cast<unsigned*>(&Bs[st][n0 + g][kk + 2 * t]);
                b[j][1] = *reinterpret_cast<unsigned*>(&Bs[st][n0 + g][kk + 2 * t + 8]);
            }
#pragma unroll
            for (int i = 0; i < 2; i++)
#pragma unroll
                for (int j = 0; j < 8; j++)
                    mma_f16(acc[i][j], a[i][0], a[i][1], a[i][2], a[i][3],
                            b[j][0], b[j][1]);
        }
        if (it + 1 < nIter) { sts_tiles((it + 1) & 1); __syncthreads(); }
    }

    if (out_half) {
        __half* C = reinterpret_cast<__half*>(Cout);
#pragma unroll
        for (int j = 0; j < 8; j++) {
            const int col = bcol + wc * 64 + j * 8 + 2 * t;
            const float b0 = bias[col], b1 = bias[col + 1];
#pragma unroll
            for (int i = 0; i < 2; i++) {
                const int r0 = brow + wr * 32 + i * 16;
                *reinterpret_cast<unsigned*>(&C[(size_t)(r0 + g) * N + col]) =
                    pack_h2(acc[i][j][0] + b0, acc[i][j][1] + b1);
                *reinterpret_cast<unsigned*>(&C[(size_t)(r0 + g + 8) * N + col]) =
                    pack_h2(acc[i][j][2] + b0, acc[i][j][3] + b1);
            }
        }
    } else {
        float* C = reinterpret_cast<float*>(Cout);
#pragma unroll
        for (int j = 0; j < 8; j++) {
            const int col = bcol + wc * 64 + j * 8 + 2 * t;
            const float b0 = bias[col], b1 = bias[col + 1];
#pragma unroll
            for (int i = 0; i < 2; i++) {
                const int r0 = brow + wr * 32 + i * 16;
                float2 o0 = {acc[i][j][0] + b0, acc[i][j][1] + b1};
                float2 o1 = {acc[i][j][2] + b0, acc[i][j][3] + b1};
                *reinterpret_cast<float2*>(&C[(size_t)(r0 + g) * N + col]) = o0;
                *reinterpret_cast<float2*>(&C[(size_t)(r0 + g + 8) * N + col]) = o1;
            }
        }
    }
}

// ---------------------------------------------------------------------------
// Fused QK^T + softmax (fp16 mma, scores scaled post-mma; single attn write).
// Block: 32 rows x 1024 keys of one (b,h). 512 threads, 16 warps (2x8).
// ---------------------------------------------------------------------------
__global__ __launch_bounds__(512) void qk_softmax_h(
    const __half* __restrict__ qkvh, float* __restrict__ attn)
{
    __shared__ __align__(16) __half Qs[32][72];
    __shared__ __align__(16) __half Ks[2][128][72];
    __shared__ float redM[32 * 9];
    __shared__ float redS[32 * 9];

    const int bh = blockIdx.y;
    const int b = bh >> 4, h = bh & 15;
    const int n0 = blockIdx.x * FROWS;

    const int tid = threadIdx.x;
    const int w = tid >> 5, l = tid & 31;
    const int g = l >> 2, t = l & 3;
    const int wr = w >> 3, wc = w & 7;

    const __half* qb = qkvh + (size_t)b * NN * 3 * CC + h * DD;
    const __half* kb = qb + CC;

    if (tid < 256) {
        const int row = tid >> 3, c8 = tid & 7;
        *reinterpret_cast<uint4*>(&Qs[row][c8 * 8]) =
            *reinterpret_cast<const uint4*>(qb + (size_t)(n0 + row) * 3 * CC + c8 * 8);
    }

    uint4 kpre[2];
    auto ldg_k = [&](int m0) {
#pragma unroll
        for (int j = 0; j < 2; j++) {
            const int idx = tid * 2 + j;
            const int m = idx >> 3, c8 = idx & 7;
            kpre[j] = *reinterpret_cast<const uint4*>(
                kb + (size_t)(m0 + m) * 3 * CC + c8 * 8);
        }
    };
    auto sts_k = [&](int st) {
#pragma unroll
        for (int j = 0; j < 2; j++) {
            const int idx = tid * 2 + j;
            const int m = idx >> 3, c8 = idx & 7;
            *reinterpret_cast<uint4*>(&Ks[st][m][c8 * 8]) = kpre[j];
        }
    };

    float acc[8][2][4];
#pragma unroll
    for (int c = 0; c < 8; c++)
#pragma unroll
        for (int jn = 0; jn < 2; jn++)
#pragma unroll
            for (int r = 0; r < 4; r++) acc[c][jn][r] = 0.0f;

    const int row0 = wr * 16 + g;
    const int row1 = row0 + 8;

    ldg_k(0);
    sts_k(0);
    __syncthreads();
#pragma unroll
    for (int c = 0; c < 8; c++) {
        if (c < 7) ldg_k((c + 1) * 128);
        const int st = c & 1;
#pragma unroll
        for (int ss = 0; ss < 4; ss++) {
            const int kk = ss * 16;
            const unsigned a0 = *reinterpret_cast<unsigned*>(&Qs[wr * 16 + g][kk + 2 * t]);
            const unsigned a1 = *reinterpret_cast<unsigned*>(&Qs[wr * 16 + g + 8][kk + 2 * t]);
            const unsigned a2 = *reinterpret_cast<unsigned*>(&Qs[wr * 16 + g][kk + 2 * t + 8]);
            const unsigned a3 = *reinterpret_cast<unsigned*>(&Qs[wr * 16 + g + 8][kk + 2 * t + 8]);
#pragma unroll
            for (int jn = 0; jn < 2; jn++) {
                const int nr = wc * 16 + jn * 8 + g;
                const unsigned b0 = *reinterpret_cast<unsigned*>(&Ks[st][nr][kk + 2 * t]);
                const unsigned b1 = *reinterpret_cast<unsigned*>(&Ks[st][nr][kk + 2 * t + 8]);
                mma_f16(acc[c][jn], a0, a1, a2, a3, b0, b1);
            }
        }
        if (c < 7) { sts_k((c + 1) & 1); __syncthreads(); }
    }

    // scale scores (exact: 0.125 = 2^-3)
#pragma unroll
    for (int c = 0; c < 8; c++)
#pragma unroll
        for (int jn = 0; jn < 2; jn++)
#pragma unroll
            for (int r = 0; r < 4; r++) acc[c][jn][r] *= SCALE;

    // ---- softmax over 1024-wide rows ----
    float mx0 = -3.402823466e+38f, mx1 = -3.402823466e+38f;
#pragma unroll
    for (int c = 0; c < 8; c++)
#pragma unroll
        for (int jn = 0; jn < 2; jn++) {
            mx0 = fmaxf(mx0, fmaxf(acc[c][jn][0], acc[c][jn][1]));
            mx1 = fmaxf(mx1, fmaxf(acc[c][jn][2], acc[c][jn][3]));
        }
#pragma unroll
    for (int o = 1; o <= 2; o <<= 1) {
        mx0 = fmaxf(mx0, __shfl_xor_sync(0xffffffffu, mx0, o));
        mx1 = fmaxf(mx1, __shfl_xor_sync(0xffffffffu, mx1, o));
    }
    if (t == 0) {
        redM[row0 * 9 + wc] = mx0;
        redM[row1 * 9 + wc] = mx1;
    }
    __syncthreads();
    mx0 = redM[row0 * 9];
    mx1 = redM[row1 * 9];
#pragma unroll
    for (int k = 1; k < 8; k++) {
        mx0 = fmaxf(mx0, redM[row0 * 9 + k]);
        mx1 = fmaxf(mx1, redM[row1 * 9 + k]);
    }

    float s0 = 0.0f, s1 = 0.0f;
#pragma unroll
    for (int c = 0; c < 8; c++)
#pragma unroll
        for (int jn = 0; jn < 2; jn++) {
            acc[c][jn][0] = __expf(acc[c][jn][0] - mx0);
            acc[c][jn][1] = __expf(acc[c][jn][1] - mx0);
            acc[c][jn][2] = __expf(acc[c][jn][2] - mx1);
            acc[c][jn][3] = __expf(acc[c][jn][3] - mx1);
            s0 += acc[c][jn][0] + acc[c][jn][1];
            s1 += acc[c][jn][2] + acc[c][jn][3];
        }
#pragma unroll
    for (int o = 1; o <= 2; o <<= 1) {
        s0 += __shfl_xor_sync(0xffffffffu, s0, o);
        s1 += __shfl_xor_sync(0xffffffffu, s1, o);
    }
    if (t == 0) {
        redS[row0 * 9 + wc] = s0;
        redS[row1 * 9 + wc] = s1;
    }
    __syncthreads();
    s0 = redS[row0 * 9];
    s1 = redS[row1 * 9];
#pragma unroll
    for (int k = 1; k < 8; k++) {
        s0 += redS[row0 * 9 + k];
        s1 += redS[row1 * 9 + k];
    }
    const float inv0 = 1.0f / s0;
    const float inv1 = 1.0f / s1;

    float* arow0 = attn + ((size_t)bh * NN + n0 + row0) * NN;
    float* arow1 = attn + ((size_t)bh * NN + n0 + row1) * NN;
#pragma unroll
    for (int c = 0; c < 8; c++)
#pragma unroll
        for (int jn = 0; jn < 2; jn++) {
            const int col = c * 128 + wc * 16 + jn * 8 + 2 * t;
            float2 o0 = {acc[c][jn][0] * inv0, acc[c][jn][1] * inv0};
            float2 o1 = {acc[c][jn][2] * inv1, acc[c][jn][3] * inv1};
            *reinterpret_cast<float2*>(&arow0[col]) = o0;
            *reinterpret_cast<float2*>(&arow1[col]) = o1;
        }
}

// ---------------------------------------------------------------------------
// PV (fp16 mma): ctx_h[b,n,h*64+d] = sum_m attn[bh,n,m] * v[bh,m,d]
// 128 rows x 64 cols, BK=32, 256 thr, warp tile 32x32. V from g_vt [d][m].
// ---------------------------------------------------------------------------
__global__ __launch_bounds__(256) void av_ctx_h(
    const float* __restrict__ attn, const __half* __restrict__ vt,
    __half* __restrict__ ctxh)
{
    __shared__ __align__(16) __half Ps[2][128][40];
    __shared__ __align__(16) __half Vs[2][64][40];

    const int bh = blockIdx.y;
    const int b = bh >> 4, h = bh & 15;
    const int n0 = blockIdx.x * 128;

    const float* ar = attn + ((size_t)bh * NN + n0) * NN;
    const __half* vb = vt + (size_t)bh * DD * NN;

    const int tid = threadIdx.x;
    const int w = tid >> 5, l = tid & 31;
    const int wr = w >> 1, wc = w & 1;
    const int g = l >> 2, t = l & 3;

    float4 p_r[4];
    uint4 v_r;
    auto ldg_tiles = [&](int k0) {
#pragma unroll
        for (int j = 0; j < 4; j++) {
            const int idx = tid * 4 + j;
            const int r = idx >> 3, c4 = idx & 7;
            p_r[j] = *reinterpret_cast<const float4*>(
                ar + (size_t)r * NN + k0 + c4 * 4);
        }
        {
            const int d = tid >> 2, c8 = tid & 3;
            v_r = *reinterpret_cast<const uint4*>(
                vb + (size_t)d * NN + k0 + c8 * 8);
        }
    };
    auto sts_tiles = [&](int st) {
#pragma unroll
        for (int j = 0; j < 4; j++) {
            const int idx = tid * 4 + j;
            const int r = idx >> 3, c4 = idx & 7;
            uint2 u;
            u.x = pack_h2(p_r[j].x, p_r[j].y);
            u.y = pack_h2(p_r[j].z, p_r[j].w);
            *reinterpret_cast<uint2*>(&Ps[st][r][c4 * 4]) = u;
        }
        {
            const int d = tid >> 2, c8 = tid & 3;
            *reinterpret_cast<uint4*>(&Vs[st][d][c8 * 8]) = v_r;
        }
    };

    float acc[2][4][4];
#pragma unroll
    for (int i = 0; i < 2; i++)
#pragma unroll
        for (int j = 0; j < 4; j++)
#pragma unroll
            for (int r = 0; r < 4; r++) acc[i][j][r] = 0.0f;

    const int nIter = NN >> 5;
    ldg_tiles(0);
    sts_tiles(0);
    __syncthreads();
    for (int it = 0; it < nIter; it++) {
        if (it + 1 < nIter) ldg_tiles((it + 1) << 5);
        const int st = it & 1;
#pragma unroll
        for (int ss = 0; ss < 2; ss++) {
            const int kk = ss * 16;
            unsigned a[2][4];
#pragma unroll
            for (int i = 0; i < 2; i++) {
                const int m = wr * 32 + i * 16;
                a[i][0] = *reinterpret_cast<unsigned*>(&Ps[st][m + g][kk + 2 * t]);
                a[i][1] = *reinterpret_cast<unsigned*>(&Ps[st][m + g + 8][kk + 2 * t]);
                a[i][2] = *reinterpret_cast<unsigned*>(&Ps[st][m + g][kk + 2 * t + 8]);
                a[i][3] = *reinterpret_cast<unsigned*>(&Ps[st][m + g + 8][kk + 2 * t + 8]);
            }
            unsigned bfr[4][2];
#pragma unroll
            for (int j = 0; j < 4; j++) {
                const int d0 = wc * 32 + j * 8;
                bfr[j][0] = *reinterpret_cast<unsigned*>(&Vs[st][d0 + g][kk + 2 * t]);
                bfr[j][1] = *reinterpret_cast<unsigned*>(&Vs[st][d0 + g][kk + 2 * t + 8]);
            }
#pragma unroll
            for (int i = 0; i < 2; i++)
#pragma unroll
                for (int j = 0; j < 4; j++)
                    mma_f16(acc[i][j], a[i][0], a[i][1], a[i][2], a[i][3],
                            bfr[j][0], bfr[j][1]);
        }
        if (it + 1 < nIter) { sts_tiles((it + 1) & 1); __syncthreads(); }
    }

#pragma unroll
    for (int j = 0; j < 4; j++) {
        const int col = h * DD + wc * 32 + j * 8 + 2 * t;
#pragma unroll
        for (int i = 0; i < 2; i++) {
            const int r0 = n0 + wr * 32 + i * 16;
            *reinterpret_cast<unsigned*>(
                &ctxh[((size_t)b * NN + r0 + g) * CC + col]) =
                pack_h2(acc[i][j][0], acc[i][j][1]);
            *reinterpret_cast<unsigned*>(
                &ctxh[((size_t)b * NN + r0 + g + 8) * CC + col]) =
                pack_h2(acc[i][j][2], acc[i][j][3]);
        }
    }
}

// ---------------------------------------------------------------------------
extern "C" void kernel_launch(void* const* d_in, const int* in_sizes, int n_in,
                              void* d_out, int out_size)
{
    (void)in_sizes; (void)n_in; (void)out_size;
    const float* x      = (const float*)d_in[0];
    const float* w_qkv  = (const float*)d_in[1];
    const float* b_qkv  = (const float*)d_in[2];
    const float* w_proj = (const float*)d_in[3];
    const float* b_proj = (const float*)d_in[4];

    float* out  = (float*)d_out;
    float* attn = out + (size_t)BB * NN * CC;

    __half *xh, *qkvh, *ctxh, *wqkvT, *wprojT, *vt;
    cudaGetSymbolAddress((void**)&xh, g_xh);
    cudaGetSymbolAddress((void**)&qkvh, g_qkvh);
    cudaGetSymbolAddress((void**)&ctxh, g_ctxh);
    cudaGetSymbolAddress((void**)&wqkvT, g_wqkvT);
    cudaGetSymbolAddress((void**)&wprojT, g_wprojT);
    cudaGetSymbolAddress((void**)&vt, g_vt);

    // 0) One-time conversions (cheap: ~50MB total traffic)
    const int nx8 = BB * NN * CC / 8;
    cvt_f32_h<<<(nx8 + 255) / 256, 256>>>(x, xh, nx8);
    transpose_w_h<<<dim3(CC / 32, 3 * CC / 32), dim3(32, 8)>>>(
        w_qkv, wqkvT, CC, 3 * CC);
    transpose_w_h<<<dim3(CC / 32, CC / 32), dim3(32, 8)>>>(
        w_proj, wprojT, CC, CC);

    // 1) QKV projection (fp16 TC, fp16 out)
    gemm_h<<<dim3(3 * CC / 128, BB * NN / 128), 256>>>(
        xh, wqkvT, b_qkv, qkvh, BB * NN, 3 * CC, CC, 1);

    // 1b) V transpose -> [bh][d][m]
    transpose_v_h<<<dim3(NN / 128, BB * HH), 256>>>(qkvh, vt);

    // 2) Fused QK^T + softmax -> attn (fp32, single write)
    qk_softmax_h<<<dim3(NN / FROWS, BB * HH), 512>>>(qkvh, attn);

    // 3) attn @ V -> ctx fp16
    av_ctx_h<<<dim3(NN / 128, BB * HH), 256>>>(attn, vt, ctxh);

    // 4) Output projection (fp16 TC, fp32 out)
    gemm_h<<<dim3(CC / 128, BB * NN / 128), 256>>>(
        ctxh, wprojT, b_proj, out, BB * NN, CC, CC, 0);
}

// round 8
// speedup vs baseline: 2.7133x; 1.0916x over previous
#include <cuda_runtime.h>
#include <cuda_fp16.h>
#include <cstdint>
#include <cstddef>

// B=8, N=1024, C=1024, H=16, D=64, scale = 0.125
#define BB 8
#define NN 1024
#define CC 1024
#define HH 16
#define DD 64
#define SCALE 0.125f
#define FROWS 32

__device__ __half g_xh[(size_t)BB * NN * CC];
__device__ __half g_qkvh[(size_t)BB * NN * 3 * CC];    // (B,N,3,H,D)
__device__ __half g_ctxh[(size_t)BB * NN * CC];
__device__ __half g_wqkvT[(size_t)3 * CC * CC];        // [n][k]
__device__ __half g_wprojT[(size_t)CC * CC];           // [n][k]
__device__ __half g_vt[(size_t)BB * HH * DD * NN];     // [bh][d][m]

__device__ __forceinline__ unsigned pack_h2(float a, float b) {
    __half2 h = __floats2half2_rn(a, b);
    return *reinterpret_cast<unsigned*>(&h);
}

__device__ __forceinline__ void mma_f16(float c[4],
    unsigned a0, unsigned a1, unsigned a2, unsigned a3,
    unsigned b0, unsigned b1)
{
    asm volatile(
        "mma.sync.aligned.m16n8k16.row.col.f32.f16.f16.f32 "
        "{%0,%1,%2,%3}, {%4,%5,%6,%7}, {%8,%9}, {%0,%1,%2,%3};\n"
        : "+f"(c[0]), "+f"(c[1]), "+f"(c[2]), "+f"(c[3])
        : "r"(a0), "r"(a1), "r"(a2), "r"(a3), "r"(b0), "r"(b1));
}

__device__ __forceinline__ void ldmx4(unsigned& r0, unsigned& r1,
                                      unsigned& r2, unsigned& r3,
                                      const void* p)
{
    unsigned addr = (unsigned)__cvta_generic_to_shared(p);
    asm volatile(
        "ldmatrix.sync.aligned.m8n8.x4.shared.b16 {%0,%1,%2,%3}, [%4];\n"
        : "=r"(r0), "=r"(r1), "=r"(r2), "=r"(r3) : "r"(addr));
}

// ---------------------------------------------------------------------------
__global__ void cvt_f32_h(const float* __restrict__ in,
                          __half* __restrict__ out, int n8)
{
    int i = blockIdx.x * blockDim.x + threadIdx.x;
    if (i >= n8) return;
    const float4* p = reinterpret_cast<const float4*>(in) + (size_t)i * 2;
    float4 v0 = p[0], v1 = p[1];
    uint4 u;
    u.x = pack_h2(v0.x, v0.y);
    u.y = pack_h2(v0.z, v0.w);
    u.z = pack_h2(v1.x, v1.y);
    u.w = pack_h2(v1.z, v1.w);
    reinterpret_cast<uint4*>(out)[i] = u;
}

__global__ void transpose_w_h(const float* __restrict__ W,
                              __half* __restrict__ WT, int K, int N)
{
    __shared__ float tile[32][33];
    const int k0 = blockIdx.x * 32, n0 = blockIdx.y * 32;
    for (int i = threadIdx.y; i < 32; i += 8)
        tile[i][threadIdx.x] = W[(size_t)(k0 + i) * N + n0 + threadIdx.x];
    __syncthreads();
    for (int i = threadIdx.y; i < 32; i += 8)
        WT[(size_t)(n0 + i) * K + k0 + threadIdx.x] =
            __float2half_rn(tile[threadIdx.x][i]);
}

__global__ __launch_bounds__(256) void transpose_v_h(
    const __half* __restrict__ qkvh, __half* __restrict__ vt)
{
    __shared__ __half tile[128][72];
    const int bh = blockIdx.y;
    const int b = bh >> 4, h = bh & 15;
    const int m0 = blockIdx.x * 128;
    const __half* vb = qkvh + (size_t)b * NN * 3 * CC + 2 * CC + h * DD;

#pragma unroll
    for (int it = 0; it < 4; it++) {
        const int idx = threadIdx.x + 256 * it;
        const int m = idx >> 3, c8 = idx & 7;
        uint4 v = *reinterpret_cast<const uint4*>(
            vb + (size_t)(m0 + m) * 3 * CC + c8 * 8);
        *reinterpret_cast<uint4*>(&tile[m][c8 * 8]) = v;
    }
    __syncthreads();
    __half* ob = vt + (size_t)bh * DD * NN + m0;
#pragma unroll
    for (int it = 0; it < 4; it++) {
        const int idx = threadIdx.x + 256 * it;
        const int d = idx >> 4, mc = idx & 15;
        __half hbuf[8];
#pragma unroll
        for (int j = 0; j < 8; j++) hbuf[j] = tile[mc * 8 + j][d];
        *reinterpret_cast<uint4*>(ob + (size_t)d * NN + mc * 8) =
            *reinterpret_cast<uint4*>(hbuf);
    }
}

// ---------------------------------------------------------------------------
// fp16 TC GEMM + bias (ldmatrix). 128x128 tile, BK=32, 256 thr, warp 32x64.
// ---------------------------------------------------------------------------
__global__ __launch_bounds__(256) void gemm_h(
    const __half* __restrict__ Ah, const __half* __restrict__ BT,
    const float* __restrict__ bias, void* __restrict__ Cout,
    int M, int N, int K, int out_half)
{
    __shared__ __align__(16) __half As[2][128][40];
    __shared__ __align__(16) __half Bs[2][128][40];

    const int tid  = threadIdx.x;
    const int brow = blockIdx.y * 128;
    const int bcol = blockIdx.x * 128;
    const int w = tid >> 5, l = tid & 31;
    const int wr = w >> 1, wc = w & 1;
    const int g = l >> 2, t = l & 3;

    const int arow = l & 15;                 // ldmatrix A row-lane
    const int acol = (l >> 4) * 8;           // ldmatrix A col-lane
    const int brow8 = ((l >> 4) * 8) + (l & 7);   // ldmatrix B row-lane
    const int bcol8 = ((l >> 3) & 1) * 8;         // ldmatrix B col-lane

    uint4 a_r[2], b_r[2];
    auto ldg_tiles = [&](int k0) {
#pragma unroll
        for (int j = 0; j < 2; j++) {
            const int idx = tid * 2 + j;
            const int row = idx >> 2, c8 = idx & 3;
            a_r[j] = *reinterpret_cast<const uint4*>(
                Ah + (size_t)(brow + row) * K + k0 + c8 * 8);
            b_r[j] = *reinterpret_cast<const uint4*>(
                BT + (size_t)(bcol + row) * K + k0 + c8 * 8);
        }
    };
    auto sts_tiles = [&](int st) {
#pragma unroll
        for (int j = 0; j < 2; j++) {
            const int idx = tid * 2 + j;
            const int row = idx >> 2, c8 = idx & 3;
            *reinterpret_cast<uint4*>(&As[st][row][c8 * 8]) = a_r[j];
            *reinterpret_cast<uint4*>(&Bs[st][row][c8 * 8]) = b_r[j];
        }
    };

    float acc[2][8][4];
#pragma unroll
    for (int i = 0; i < 2; i++)
#pragma unroll
        for (int j = 0; j < 8; j++)
#pragma unroll
            for (int r = 0; r < 4; r++) acc[i][j][r] = 0.0f;

    const int nIter = K >> 5;
    ldg_tiles(0);
    sts_tiles(0);
    __syncthreads();
    for (int it = 0; it < nIter; it++) {
        if (it + 1 < nIter) ldg_tiles((it + 1) << 5);
        const int st = it & 1;
#pragma unroll
        for (int ss = 0; ss < 2; ss++) {
            const int kk = ss * 16;
            unsigned a[2][4], b[8][2];
#pragma unroll
            for (int i = 0; i < 2; i++)
                ldmx4(a[i][0], a[i][1], a[i][2], a[i][3],
                      &As[st][wr * 32 + i * 16 + arow][kk + acol]);
#pragma unroll
            for (int jp = 0; jp < 4; jp++)
                ldmx4(b[jp * 2][0], b[jp * 2][1], b[jp * 2 + 1][0], b[jp * 2 + 1][1],
                      &Bs[st][wc * 64 + jp * 16 + brow8][kk + bcol8]);
#pragma unroll
            for (int i = 0; i < 2; i++)
#pragma unroll
                for (int j = 0; j < 8; j++)
                    mma_f16(acc[i][j], a[i][0], a[i][1], a[i][2], a[i][3],
                            b[j][0], b[j][1]);
        }
        if (it + 1 < nIter) { sts_tiles((it + 1) & 1); __syncthreads(); }
    }

    if (out_half) {
        __half* C = reinterpret_cast<__half*>(Cout);
#pragma unroll
        for (int j = 0; j < 8; j++) {
            const int col = bcol + wc * 64 + j * 8 + 2 * t;
            const float b0 = bias[col], b1 = bias[col + 1];
#pragma unroll
            for (int i = 0; i < 2; i++) {
                const int r0 = brow + wr * 32 + i * 16;
                *reinterpret_cast<unsigned*>(&C[(size_t)(r0 + g) * N + col]) =
                    pack_h2(acc[i][j][0] + b0, acc[i][j][1] + b1);
                *reinterpret_cast<unsigned*>(&C[(size_t)(r0 + g + 8) * N + col]) =
                    pack_h2(acc[i][j][2] + b0, acc[i][j][3] + b1);
            }
        }
    } else {
        float* C = reinterpret_cast<float*>(Cout);
#pragma unroll
        for (int j = 0; j < 8; j++) {
            const int col = bcol + wc * 64 + j * 8 + 2 * t;
            const float b0 = bias[col], b1 = bias[col + 1];
#pragma unroll
            for (int i = 0; i < 2; i++) {
                const int r0 = brow + wr * 32 + i * 16;
                float2 o0 = {acc[i][j][0] + b0, acc[i][j][1] + b1};
                float2 o1 = {acc[i][j][2] + b0, acc[i][j][3] + b1};
                *reinterpret_cast<float2*>(&C[(size_t)(r0 + g) * N + col]) = o0;
                *reinterpret_cast<float2*>(&C[(size_t)(r0 + g + 8) * N + col]) = o1;
            }
        }
    }
}

// ---------------------------------------------------------------------------
// Fused QK^T + softmax (fp16 mma + ldmatrix, Q frags hoisted to registers).
// Block: 32 rows x 1024 keys of one (b,h). 512 threads, 16 warps (2x8).
// ---------------------------------------------------------------------------
__global__ __launch_bounds__(512) void qk_softmax_h(
    const __half* __restrict__ qkvh, float* __restrict__ attn)
{
    __shared__ __align__(16) __half Qs[32][72];
    __shared__ __align__(16) __half Ks[2][128][72];
    __shared__ float redM[32 * 9];
    __shared__ float redS[32 * 9];

    const int bh = blockIdx.y;
    const int b = bh >> 4, h = bh & 15;
    const int n0 = blockIdx.x * FROWS;

    const int tid = threadIdx.x;
    const int w = tid >> 5, l = tid & 31;
    const int g = l >> 2, t = l & 3;
    const int wr = w >> 3, wc = w & 7;

    const int arow = l & 15;
    const int acol = (l >> 4) * 8;
    const int brow8 = ((l >> 4) * 8) + (l & 7);
    const int bcol8 = ((l >> 3) & 1) * 8;

    const __half* qb = qkvh + (size_t)b * NN * 3 * CC + h * DD;
    const __half* kb = qb + CC;

    if (tid < 256) {
        const int row = tid >> 3, c8 = tid & 7;
        *reinterpret_cast<uint4*>(&Qs[row][c8 * 8]) =
            *reinterpret_cast<const uint4*>(qb + (size_t)(n0 + row) * 3 * CC + c8 * 8);
    }

    uint4 kpre[2];
    auto ldg_k = [&](int m0) {
#pragma unroll
        for (int j = 0; j < 2; j++) {
            const int idx = tid * 2 + j;
            const int m = idx >> 3, c8 = idx & 7;
            kpre[j] = *reinterpret_cast<const uint4*>(
                kb + (size_t)(m0 + m) * 3 * CC + c8 * 8);
        }
    };
    auto sts_k = [&](int st) {
#pragma unroll
        for (int j = 0; j < 2; j++) {
            const int idx = tid * 2 + j;
            const int m = idx >> 3, c8 = idx & 7;
            *reinterpret_cast<uint4*>(&Ks[st][m][c8 * 8]) = kpre[j];
        }
    };

    float acc[8][2][4];
#pragma unroll
    for (int c = 0; c < 8; c++)
#pragma unroll
        for (int jn = 0; jn < 2; jn++)
#pragma unroll
            for (int r = 0; r < 4; r++) acc[c][jn][r] = 0.0f;

    const int row0 = wr * 16 + g;
    const int row1 = row0 + 8;

    ldg_k(0);
    sts_k(0);
    __syncthreads();

    // Hoist Q fragments (invariant over key loop): 4 k16-slabs
    unsigned qa[4][4];
#pragma unroll
    for (int ss = 0; ss < 4; ss++)
        ldmx4(qa[ss][0], qa[ss][1], qa[ss][2], qa[ss][3],
              &Qs[wr * 16 + arow][ss * 16 + acol]);

#pragma unroll
    for (int c = 0; c < 8; c++) {
        if (c < 7) ldg_k((c + 1) * 128);
        const int st = c & 1;
#pragma unroll
        for (int ss = 0; ss < 4; ss++) {
            const int kk = ss * 16;
            unsigned kb0, kb1, kb2, kb3;
            ldmx4(kb0, kb1, kb2, kb3,
                  &Ks[st][wc * 16 + brow8][kk + bcol8]);
            mma_f16(acc[c][0], qa[ss][0], qa[ss][1], qa[ss][2], qa[ss][3], kb0, kb1);
            mma_f16(acc[c][1], qa[ss][0], qa[ss][1], qa[ss][2], qa[ss][3], kb2, kb3);
        }
        if (c < 7) { sts_k((c + 1) & 1); __syncthreads(); }
    }

#pragma unroll
    for (int c = 0; c < 8; c++)
#pragma unroll
        for (int jn = 0; jn < 2; jn++)
#pragma unroll
            for (int r = 0; r < 4; r++) acc[c][jn][r] *= SCALE;

    // ---- softmax ----
    float mx0 = -3.402823466e+38f, mx1 = -3.402823466e+38f;
#pragma unroll
    for (int c = 0; c < 8; c++)
#pragma unroll
        for (int jn = 0; jn < 2; jn++) {
            mx0 = fmaxf(mx0, fmaxf(acc[c][jn][0], acc[c][jn][1]));
            mx1 = fmaxf(mx1, fmaxf(acc[c][jn][2], acc[c][jn][3]));
        }
#pragma unroll
    for (int o = 1; o <= 2; o <<= 1) {
        mx0 = fmaxf(mx0, __shfl_xor_sync(0xffffffffu, mx0, o));
        mx1 = fmaxf(mx1, __shfl_xor_sync(0xffffffffu, mx1, o));
    }
    if (t == 0) {
        redM[row0 * 9 + wc] = mx0;
        redM[row1 * 9 + wc] = mx1;
    }
    __syncthreads();
    mx0 = redM[row0 * 9];
    mx1 = redM[row1 * 9];
#pragma unroll
    for (int k = 1; k < 8; k++) {
        mx0 = fmaxf(mx0, redM[row0 * 9 + k]);
        mx1 = fmaxf(mx1, redM[row1 * 9 + k]);
    }

    float s0 = 0.0f, s1 = 0.0f;
#pragma unroll
    for (int c = 0; c < 8; c++)
#pragma unroll
        for (int jn = 0; jn < 2; jn++) {
            acc[c][jn][0] = __expf(acc[c][jn][0] - mx0);
            acc[c][jn][1] = __expf(acc[c][jn][1] - mx0);
            acc[c][jn][2] = __expf(acc[c][jn][2] - mx1);
            acc[c][jn][3] = __expf(acc[c][jn][3] - mx1);
            s0 += acc[c][jn][0] + acc[c][jn][1];
            s1 += acc[c][jn][2] + acc[c][jn][3];
        }
#pragma unroll
    for (int o = 1; o <= 2; o <<= 1) {
        s0 += __shfl_xor_sync(0xffffffffu, s0, o);
        s1 += __shfl_xor_sync(0xffffffffu, s1, o);
    }
    if (t == 0) {
        redS[row0 * 9 + wc] = s0;
        redS[row1 * 9 + wc] = s1;
    }
    __syncthreads();
    s0 = redS[row0 * 9];
    s1 = redS[row1 * 9];
#pragma unroll
    for (int k = 1; k < 8; k++) {
        s0 += redS[row0 * 9 + k];
        s1 += redS[row1 * 9 + k];
    }
    const float inv0 = 1.0f / s0;
    const float inv1 = 1.0f / s1;

    float* arow0 = attn + ((size_t)bh * NN + n0 + row0) * NN;
    float* arow1 = attn + ((size_t)bh * NN + n0 + row1) * NN;
#pragma unroll
    for (int c = 0; c < 8; c++)
#pragma unroll
        for (int jn = 0; jn < 2; jn++) {
            const int col = c * 128 + wc * 16 + jn * 8 + 2 * t;
            float2 o0 = {acc[c][jn][0] * inv0, acc[c][jn][1] * inv0};
            float2 o1 = {acc[c][jn][2] * inv1, acc[c][jn][3] * inv1};
            *reinterpret_cast<float2*>(&arow0[col]) = o0;
            *reinterpret_cast<float2*>(&arow1[col]) = o1;
        }
}

// ---------------------------------------------------------------------------
// PV (fp16 mma + ldmatrix): 128 rows x 64 cols, BK=32, 256 thr, warp 32x32.
// ---------------------------------------------------------------------------
__global__ __launch_bounds__(256) void av_ctx_h(
    const float* __restrict__ attn, const __half* __restrict__ vt,
    __half* __restrict__ ctxh)
{
    __shared__ __align__(16) __half Ps[2][128][40];
    __shared__ __align__(16) __half Vs[2][64][40];

    const int bh = blockIdx.y;
    const int b = bh >> 4, h = bh & 15;
    const int n0 = blockIdx.x * 128;

    const float* ar = attn + ((size_t)bh * NN + n0) * NN;
    const __half* vb = vt + (size_t)bh * DD * NN;

    const int tid = threadIdx.x;
    const int w = tid >> 5, l = tid & 31;
    const int wr = w >> 1, wc = w & 1;
    const int g = l >> 2, t = l & 3;

    const int arow = l & 15;
    const int acol = (l >> 4) * 8;
    const int brow8 = ((l >> 4) * 8) + (l & 7);
    const int bcol8 = ((l >> 3) & 1) * 8;

    float4 p_r[4];
    uint4 v_r;
    auto ldg_tiles = [&](int k0) {
#pragma unroll
        for (int j = 0; j < 4; j++) {
            const int idx = tid * 4 + j;
            const int r = idx >> 3, c4 = idx & 7;
            p_r[j] = *reinterpret_cast<const float4*>(
                ar + (size_t)r * NN + k0 + c4 * 4);
        }
        {
            const int d = tid >> 2, c8 = tid & 3;
            v_r = *reinterpret_cast<const uint4*>(
                vb + (size_t)d * NN + k0 + c8 * 8);
        }
    };
    auto sts_tiles = [&](int st) {
#pragma unroll
        for (int j = 0; j < 4; j++) {
            const int idx = tid * 4 + j;
            const int r = idx >> 3, c4 = idx & 7;
            uint2 u;
            u.x = pack_h2(p_r[j].x, p_r[j].y);
            u.y = pack_h2(p_r[j].z, p_r[j].w);
            *reinterpret_cast<uint2*>(&Ps[st][r][c4 * 4]) = u;
        }
        {
            const int d = tid >> 2, c8 = tid & 3;
            *reinterpret_cast<uint4*>(&Vs[st][d][c8 * 8]) = v_r;
        }
    };

    float acc[2][4][4];
#pragma unroll
    for (int i = 0; i < 2; i++)
#pragma unroll
        for (int j = 0; j < 4; j++)
#pragma unroll
            for (int r = 0; r < 4; r++) acc[i][j][r] = 0.0f;

    const int nIter = NN >> 5;
    ldg_tiles(0);
    sts_tiles(0);
    __syncthreads();
    for (int it = 0; it < nIter; it++) {
        if (it + 1 < nIter) ldg_tiles((it + 1) << 5);
        const int st = it & 1;
#pragma unroll
        for (int ss = 0; ss < 2; ss++) {
            const int kk = ss * 16;
            unsigned a[2][4], bfr[4][2];
#pragma unroll
            for (int i = 0; i < 2; i++)
                ldmx4(a[i][0], a[i][1], a[i][2], a[i][3],
                      &Ps[st][wr * 32 + i * 16 + arow][kk + acol]);
#pragma unroll
            for (int jp = 0; jp < 2; jp++)
                ldmx4(bfr[jp * 2][0], bfr[jp * 2][1],
                      bfr[jp * 2 + 1][0], bfr[jp * 2 + 1][1],
                      &Vs[st][wc * 32 + jp * 16 + brow8][kk + bcol8]);
#pragma unroll
            for (int i = 0; i < 2; i++)
#pragma unroll
                for (int j = 0; j < 4; j++)
                    mma_f16(acc[i][j], a[i][0], a[i][1], a[i][2], a[i][3],
                            bfr[j][0], bfr[j][1]);
        }
        if (it + 1 < nIter) { sts_tiles((it + 1) & 1); __syncthreads(); }
    }

#pragma unroll
    for (int j = 0; j < 4; j++) {
        const int col = h * DD + wc * 32 + j * 8 + 2 * t;
#pragma unroll
        for (int i = 0; i < 2; i++) {
            const int r0 = n0 + wr * 32 + i * 16;
            *reinterpret_cast<unsigned*>(
                &ctxh[((size_t)b * NN + r0 + g) * CC + col]) =
                pack_h2(acc[i][j][0], acc[i][j][1]);
            *reinterpret_cast<unsigned*>(
                &ctxh[((size_t)b * NN + r0 + g + 8) * CC + col]) =
                pack_h2(acc[i][j][2], acc[i][j][3]);
        }
    }
}

// ---------------------------------------------------------------------------
extern "C" void kernel_launch(void* const* d_in, const int* in_sizes, int n_in,
                              void* d_out, int out_size)
{
    (void)in_sizes; (void)n_in; (void)out_size;
    const float* x      = (const float*)d_in[0];
    const float* w_qkv  = (const float*)d_in[1];
    const float* b_qkv  = (const float*)d_in[2];
    const float* w_proj = (const float*)d_in[3];
    const float* b_proj = (const float*)d_in[4];

    float* out  = (float*)d_out;
    float* attn = out + (size_t)BB * NN * CC;

    __half *xh, *qkvh, *ctxh, *wqkvT, *wprojT, *vt;
    cudaGetSymbolAddress((void**)&xh, g_xh);
    cudaGetSymbolAddress((void**)&qkvh, g_qkvh);
    cudaGetSymbolAddress((void**)&ctxh, g_ctxh);
    cudaGetSymbolAddress((void**)&wqkvT, g_wqkvT);
    cudaGetSymbolAddress((void**)&wprojT, g_wprojT);
    cudaGetSymbolAddress((void**)&vt, g_vt);

    // 0) One-time conversions
    const int nx8 = BB * NN * CC / 8;
    cvt_f32_h<<<(nx8 + 255) / 256, 256>>>(x, xh, nx8);
    transpose_w_h<<<dim3(CC / 32, 3 * CC / 32), dim3(32, 8)>>>(
        w_qkv, wqkvT, CC, 3 * CC);
    transpose_w_h<<<dim3(CC / 32, CC / 32), dim3(32, 8)>>>(
        w_proj, wprojT, CC, CC);

    // 1) QKV projection (fp16 out)
    gemm_h<<<dim3(3 * CC / 128, BB * NN / 128), 256>>>(
        xh, wqkvT, b_qkv, qkvh, BB * NN, 3 * CC, CC, 1);

    // 1b) V transpose -> [bh][d][m]
    transpose_v_h<<<dim3(NN / 128, BB * HH), 256>>>(qkvh, vt);

    // 2) Fused QK^T + softmax -> attn (single write)
    qk_softmax_h<<<dim3(NN / FROWS, BB * HH), 512>>>(qkvh, attn);

    // 3) attn @ V -> ctx fp16
    av_ctx_h<<<dim3(NN / 128, BB * HH), 256>>>(attn, vt, ctxh);

    // 4) Output projection (fp32 out)
    gemm_h<<<dim3(CC / 128, BB * NN / 128), 256>>>(
        ctxh, wprojT, b_proj, out, BB * NN, CC, CC, 0);
}

// round 10
// speedup vs baseline: 2.9004x; 1.0689x over previous
#include <cuda_runtime.h>
#include <cuda_fp16.h>
#include <cstdint>
#include <cstddef>

// B=8, N=1024, C=1024, H=16, D=64, scale = 0.125
#define BB 8
#define NN 1024
#define CC 1024
#define HH 16
#define DD 64
#define SCALE 0.125f
#define FROWS 32

__device__ __half g_xh[(size_t)BB * NN * CC];
__device__ __half g_qkvh[(size_t)BB * NN * 3 * CC];    // (B,N,3,H,D)
__device__ __half g_ctxh[(size_t)BB * NN * CC];
__device__ __half g_wqkvT[(size_t)3 * CC * CC];        // [n][k]
__device__ __half g_wprojT[(size_t)CC * CC];           // [n][k]
__device__ __half g_vt[(size_t)BB * HH * DD * NN];     // [bh][d][m]

__device__ __forceinline__ unsigned pack_h2(float a, float b) {
    __half2 h = __floats2half2_rn(a, b);
    return *reinterpret_cast<unsigned*>(&h);
}

__device__ __forceinline__ void mma_f16(float c[4],
    unsigned a0, unsigned a1, unsigned a2, unsigned a3,
    unsigned b0, unsigned b1)
{
    asm volatile(
        "mma.sync.aligned.m16n8k16.row.col.f32.f16.f16.f32 "
        "{%0,%1,%2,%3}, {%4,%5,%6,%7}, {%8,%9}, {%0,%1,%2,%3};\n"
        : "+f"(c[0]), "+f"(c[1]), "+f"(c[2]), "+f"(c[3])
        : "r"(a0), "r"(a1), "r"(a2), "r"(a3), "r"(b0), "r"(b1));
}

__device__ __forceinline__ void ldmx4(unsigned& r0, unsigned& r1,
                                      unsigned& r2, unsigned& r3,
                                      const void* p)
{
    unsigned addr = (unsigned)__cvta_generic_to_shared(p);
    asm volatile(
        "ldmatrix.sync.aligned.m8n8.x4.shared.b16 {%0,%1,%2,%3}, [%4];\n"
        : "=r"(r0), "=r"(r1), "=r"(r2), "=r"(r3) : "r"(addr));
}

__device__ __forceinline__ void cp16(void* smem, const void* gmem) {
    unsigned s = (unsigned)__cvta_generic_to_shared(smem);
    asm volatile("cp.async.cg.shared.global [%0], [%1], 16;\n"
                 :: "r"(s), "l"(gmem) : "memory");
}

// ---------------------------------------------------------------------------
__global__ void cvt_f32_h(const float* __restrict__ in,
                          __half* __restrict__ out, int n8)
{
    int i = blockIdx.x * blockDim.x + threadIdx.x;
    if (i >= n8) return;
    const float4* p = reinterpret_cast<const float4*>(in) + (size_t)i * 2;
    float4 v0 = p[0], v1 = p[1];
    uint4 u;
    u.x = pack_h2(v0.x, v0.y);
    u.y = pack_h2(v0.z, v0.w);
    u.z = pack_h2(v1.x, v1.y);
    u.w = pack_h2(v1.z, v1.w);
    reinterpret_cast<uint4*>(out)[i] = u;
}

__global__ void transpose_w_h(const float* __restrict__ W,
                              __half* __restrict__ WT, int K, int N)
{
    __shared__ float tile[32][33];
    const int k0 = blockIdx.x * 32, n0 = blockIdx.y * 32;
    for (int i = threadIdx.y; i < 32; i += 8)
        tile[i][threadIdx.x] = W[(size_t)(k0 + i) * N + n0 + threadIdx.x];
    __syncthreads();
    for (int i = threadIdx.y; i < 32; i += 8)
        WT[(size_t)(n0 + i) * K + k0 + threadIdx.x] =
            __float2half_rn(tile[threadIdx.x][i]);
}

__global__ __launch_bounds__(256) void transpose_v_h(
    const __half* __restrict__ qkvh, __half* __restrict__ vt)
{
    __shared__ __half tile[128][72];
    const int bh = blockIdx.y;
    const int b = bh >> 4, h = bh & 15;
    const int m0 = blockIdx.x * 128;
    const __half* vb = qkvh + (size_t)b * NN * 3 * CC + 2 * CC + h * DD;

#pragma unroll
    for (int it = 0; it < 4; it++) {
        const int idx = threadIdx.x + 256 * it;
        const int m = idx >> 3, c8 = idx & 7;
        uint4 v = *reinterpret_cast<const uint4*>(
            vb + (size_t)(m0 + m) * 3 * CC + c8 * 8);
        *reinterpret_cast<uint4*>(&tile[m][c8 * 8]) = v;
    }
    __syncthreads();
    __half* ob = vt + (size_t)bh * DD * NN + m0;
#pragma unroll
    for (int it = 0; it < 4; it++) {
        const int idx = threadIdx.x + 256 * it;
        const int d = idx >> 4, mc = idx & 15;
        __half hbuf[8];
#pragma unroll
        for (int j = 0; j < 8; j++) hbuf[j] = tile[mc * 8 + j][d];
        *reinterpret_cast<uint4*>(ob + (size_t)d * NN + mc * 8) =
            *reinterpret_cast<uint4*>(hbuf);
    }
}

// ---------------------------------------------------------------------------
// fp16 TC GEMM + bias: C[M,N] = Ah[M,K] @ BT[N,K]^T + bias
// CTA 256x128, 256 thr (8 warps 4x2), warp tile 64x64, BK=32,
// 3-stage cp.async pipeline, ldmatrix fragment loads.
// Dyn smem: A 3*[256][40] + B 3*[128][40] halves = 92160 B.
// ---------------------------------------------------------------------------
__global__ __launch_bounds__(256) void gemm_h2(
    const __half* __restrict__ Ah, const __half* __restrict__ BT,
    const float* __restrict__ bias, void* __restrict__ Cout,
    int M, int N, int K, int out_half)
{
    extern __shared__ __align__(16) char dsm[];
    char* sA = dsm;                       // 3 stages * 256*80 B
    char* sB = dsm + 3 * 256 * 80;        // 3 stages * 128*80 B

    const int tid  = threadIdx.x;
    const int brow = blockIdx.y * 256;
    const int bcol = blockIdx.x * 128;
    const int w = tid >> 5, l = tid & 31;
    const int wr = w >> 1, wc = w & 1;    // warp: rows wr*64, cols wc*64
    const int g = l >> 2, t = l & 3;

    const int arow = l & 15;
    const int acol = (l >> 4) * 8;
    const int brow8 = ((l >> 4) * 8) + (l & 7);
    const int bcol8 = ((l >> 3) & 1) * 8;

    auto cp_stage = [&](int kc, int st) {
        const int k0 = kc << 5;
#pragma unroll
        for (int j = 0; j < 4; j++) {
            const int i = tid + 256 * j;
            const int r = i >> 2, c = i & 3;
            cp16(sA + st * 20480 + r * 80 + c * 16,
                 Ah + (size_t)(brow + r) * K + k0 + c * 8);
        }
#pragma unroll
        for (int j = 0; j < 2; j++) {
            const int i = tid + 256 * j;
            const int r = i >> 2, c = i & 3;
            cp16(sB + st * 10240 + r * 80 + c * 16,
                 BT + (size_t)(bcol + r) * K + k0 + c * 8);
        }
        asm volatile("cp.async.commit_group;\n" ::: "memory");
    };

    float acc[4][8][4];
#pragma unroll
    for (int i = 0; i < 4; i++)
#pragma unroll
        for (int j = 0; j < 8; j++)
#pragma unroll
            for (int r = 0; r < 4; r++) acc[i][j][r] = 0.0f;

    const int nIter = K >> 5;
    cp_stage(0, 0);
    cp_stage(1, 1);
    for (int it = 0; it < nIter; it++) {
        asm volatile("cp.async.wait_group 1;\n" ::: "memory");
        __syncthreads();
        const int st = it % 3;
        const __half* pA = reinterpret_cast<const __half*>(sA + st * 20480);
        const __half* pB = reinterpret_cast<const __half*>(sB + st * 10240);
#pragma unroll
        for (int ss = 0; ss < 2; ss++) {
            const int kk = ss * 16;
            unsigned a[4][4], b[8][2];
#pragma unroll
            for (int i = 0; i < 4; i++)
                ldmx4(a[i][0], a[i][1], a[i][2], a[i][3],
                      pA + (wr * 64 + i * 16 + arow) * 40 + kk + acol);
#pragma unroll
            for (int jp = 0; jp < 4; jp++)
                ldmx4(b[jp * 2][0], b[jp * 2][1],
                      b[jp * 2 + 1][0], b[jp * 2 + 1][1],
                      pB + (wc * 64 + jp * 16 + brow8) * 40 + kk + bcol8);
#pragma unroll
            for (int i = 0; i < 4; i++)
#pragma unroll
                for (int j = 0; j < 8; j++)
                    mma_f16(acc[i][j], a[i][0], a[i][1], a[i][2], a[i][3],
                            b[j][0], b[j][1]);
        }
        if (it + 2 < nIter) cp_stage(it + 2, (it + 2) % 3);
    }

    if (out_half) {
        __half* C = reinterpret_cast<__half*>(Cout);
#pragma unroll
        for (int j = 0; j < 8; j++) {
            const int col = bcol + wc * 64 + j * 8 + 2 * t;
            const float b0 = bias[col], b1 = bias[col + 1];
#pragma unroll
            for (int i = 0; i < 4; i++) {
                const int r0 = brow + wr * 64 + i * 16;
                *reinterpret_cast<unsigned*>(&C[(size_t)(r0 + g) * N + col]) =
                    pack_h2(acc[i][j][0] + b0, acc[i][j][1] + b1);
                *reinterpret_cast<unsigned*>(&C[(size_t)(r0 + g + 8) * N + col]) =
                    pack_h2(acc[i][j][2] + b0, acc[i][j][3] + b1);
            }
        }
    } else {
        float* C = reinterpret_cast<float*>(Cout);
#pragma unroll
        for (int j = 0; j < 8; j++) {
            const int col = bcol + wc * 64 + j * 8 + 2 * t;
            const float b0 = bias[col], b1 = bias[col + 1];
#pragma unroll
            for (int i = 0; i < 4; i++) {
                const int r0 = brow + wr * 64 + i * 16;
                float2 o0 = {acc[i][j][0] + b0, acc[i][j][1] + b1};
                float2 o1 = {acc[i][j][2] + b0, acc[i][j][3] + b1};
                *reinterpret_cast<float2*>(&C[(size_t)(r0 + g) * N + col]) = o0;
                *reinterpret_cast<float2*>(&C[(size_t)(r0 + g + 8) * N + col]) = o1;
            }
        }
    }
}

// ---------------------------------------------------------------------------
// Fused QK^T + softmax (fp16 mma + ldmatrix, Q frags hoisted). Unchanged R8.
// ---------------------------------------------------------------------------
__global__ __launch_bounds__(512) void qk_softmax_h(
    const __half* __restrict__ qkvh, float* __restrict__ attn)
{
    __shared__ __align__(16) __half Qs[32][72];
    __shared__ __align__(16) __half Ks[2][128][72];
    __shared__ float redM[32 * 9];
    __shared__ float redS[32 * 9];

    const int bh = blockIdx.y;
    const int b = bh >> 4, h = bh & 15;
    const int n0 = blockIdx.x * FROWS;

    const int tid = threadIdx.x;
    const int w = tid >> 5, l = tid & 31;
    const int g = l >> 2, t = l & 3;
    const int wr = w >> 3, wc = w & 7;

    const int arow = l & 15;
    const int acol = (l >> 4) * 8;
    const int brow8 = ((l >> 4) * 8) + (l & 7);
    const int bcol8 = ((l >> 3) & 1) * 8;

    const __half* qb = qkvh + (size_t)b * NN * 3 * CC + h * DD;
    const __half* kb = qb + CC;

    if (tid < 256) {
        const int row = tid >> 3, c8 = tid & 7;
        *reinterpret_cast<uint4*>(&Qs[row][c8 * 8]) =
            *reinterpret_cast<const uint4*>(qb + (size_t)(n0 + row) * 3 * CC + c8 * 8);
    }

    uint4 kpre[2];
    auto ldg_k = [&](int m0) {
#pragma unroll
        for (int j = 0; j < 2; j++) {
            const int idx = tid * 2 + j;
            const int m = idx >> 3, c8 = idx & 7;
            kpre[j] = *reinterpret_cast<const uint4*>(
                kb + (size_t)(m0 + m) * 3 * CC + c8 * 8);
        }
    };
    auto sts_k = [&](int st) {
#pragma unroll
        for (int j = 0; j < 2; j++) {
            const int idx = tid * 2 + j;
            const int m = idx >> 3, c8 = idx & 7;
            *reinterpret_cast<uint4*>(&Ks[st][m][c8 * 8]) = kpre[j];
        }
    };

    float acc[8][2][4];
#pragma unroll
    for (int c = 0; c < 8; c++)
#pragma unroll
        for (int jn = 0; jn < 2; jn++)
#pragma unroll
            for (int r = 0; r < 4; r++) acc[c][jn][r] = 0.0f;

    const int row0 = wr * 16 + g;
    const int row1 = row0 + 8;

    ldg_k(0);
    sts_k(0);
    __syncthreads();

    unsigned qa[4][4];
#pragma unroll
    for (int ss = 0; ss < 4; ss++)
        ldmx4(qa[ss][0], qa[ss][1], qa[ss][2], qa[ss][3],
              &Qs[wr * 16 + arow][ss * 16 + acol]);

#pragma unroll
    for (int c = 0; c < 8; c++) {
        if (c < 7) ldg_k((c + 1) * 128);
        const int st = c & 1;
#pragma unroll
        for (int ss = 0; ss < 4; ss++) {
            const int kk = ss * 16;
            unsigned kb0, kb1, kb2, kb3;
            ldmx4(kb0, kb1, kb2, kb3,
                  &Ks[st][wc * 16 + brow8][kk + bcol8]);
            mma_f16(acc[c][0], qa[ss][0], qa[ss][1], qa[ss][2], qa[ss][3], kb0, kb1);
            mma_f16(acc[c][1], qa[ss][0], qa[ss][1], qa[ss][2], qa[ss][3], kb2, kb3);
        }
        if (c < 7) { sts_k((c + 1) & 1); __syncthreads(); }
    }

#pragma unroll
    for (int c = 0; c < 8; c++)
#pragma unroll
        for (int jn = 0; jn < 2; jn++)
#pragma unroll
            for (int r = 0; r < 4; r++) acc[c][jn][r] *= SCALE;

    float mx0 = -3.402823466e+38f, mx1 = -3.402823466e+38f;
#pragma unroll
    for (int c = 0; c < 8; c++)
#pragma unroll
        for (int jn = 0; jn < 2; jn++) {
            mx0 = fmaxf(mx0, fmaxf(acc[c][jn][0], acc[c][jn][1]));
            mx1 = fmaxf(mx1, fmaxf(acc[c][jn][2], acc[c][jn][3]));
        }
#pragma unroll
    for (int o = 1; o <= 2; o <<= 1) {
        mx0 = fmaxf(mx0, __shfl_xor_sync(0xffffffffu, mx0, o));
        mx1 = fmaxf(mx1, __shfl_xor_sync(0xffffffffu, mx1, o));
    }
    if (t == 0) {
        redM[row0 * 9 + wc] = mx0;
        redM[row1 * 9 + wc] = mx1;
    }
    __syncthreads();
    mx0 = redM[row0 * 9];
    mx1 = redM[row1 * 9];
#pragma unroll
    for (int k = 1; k < 8; k++) {
        mx0 = fmaxf(mx0, redM[row0 * 9 + k]);
        mx1 = fmaxf(mx1, redM[row1 * 9 + k]);
    }

    float s0 = 0.0f, s1 = 0.0f;
#pragma unroll
    for (int c = 0; c < 8; c++)
#pragma unroll
        for (int jn = 0; jn < 2; jn++) {
            acc[c][jn][0] = __expf(acc[c][jn][0] - mx0);
            acc[c][jn][1] = __expf(acc[c][jn][1] - mx0);
            acc[c][jn][2] = __expf(acc[c][jn][2] - mx1);
            acc[c][jn][3] = __expf(acc[c][jn][3] - mx1);
            s0 += acc[c][jn][0] + acc[c][jn][1];
            s1 += acc[c][jn][2] + acc[c][jn][3];
        }
#pragma unroll
    for (int o = 1; o <= 2; o <<= 1) {
        s0 += __shfl_xor_sync(0xffffffffu, s0, o);
        s1 += __shfl_xor_sync(0xffffffffu, s1, o);
    }
    if (t == 0) {
        redS[row0 * 9 + wc] = s0;
        redS[row1 * 9 + wc] = s1;
    }
    __syncthreads();
    s0 = redS[row0 * 9];
    s1 = redS[row1 * 9];
#pragma unroll
    for (int k = 1; k < 8; k++) {
        s0 += redS[row0 * 9 + k];
        s1 += redS[row1 * 9 + k];
    }
    const float inv0 = 1.0f / s0;
    const float inv1 = 1.0f / s1;

    float* arow0 = attn + ((size_t)bh * NN + n0 + row0) * NN;
    float* arow1 = attn + ((size_t)bh * NN + n0 + row1) * NN;
#pragma unroll
    for (int c = 0; c < 8; c++)
#pragma unroll
        for (int jn = 0; jn < 2; jn++) {
            const int col = c * 128 + wc * 16 + jn * 8 + 2 * t;
            float2 o0 = {acc[c][jn][0] * inv0, acc[c][jn][1] * inv0};
            float2 o1 = {acc[c][jn][2] * inv1, acc[c][jn][3] * inv1};
            *reinterpret_cast<float2*>(&arow0[col]) = o0;
            *reinterpret_cast<float2*>(&arow1[col]) = o1;
        }
}

// ---------------------------------------------------------------------------
// PV (fp16 mma + ldmatrix). Unchanged R8.
// ---------------------------------------------------------------------------
__global__ __launch_bounds__(256) void av_ctx_h(
    const float* __restrict__ attn, const __half* __restrict__ vt,
    __half* __restrict__ ctxh)
{
    __shared__ __align__(16) __half Ps[2][128][40];
    __shared__ __align__(16) __half Vs[2][64][40];

    const int bh = blockIdx.y;
    const int b = bh >> 4, h = bh & 15;
    const int n0 = blockIdx.x * 128;

    const float* ar = attn + ((size_t)bh * NN + n0) * NN;
    const __half* vb = vt + (size_t)bh * DD * NN;

    const int tid = threadIdx.x;
    const int w = tid >> 5, l = tid & 31;
    const int wr = w >> 1, wc = w & 1;
    const int g = l >> 2, t = l & 3;

    const int arow = l & 15;
    const int acol = (l >> 4) * 8;
    const int brow8 = ((l >> 4) * 8) + (l & 7);
    const int bcol8 = ((l >> 3) & 1) * 8;

    float4 p_r[4];
    uint4 v_r;
    auto ldg_tiles = [&](int k0) {
#pragma unroll
        for (int j = 0; j < 4; j++) {
            const int idx = tid * 4 + j;
            const int r = idx >> 3, c4 = idx & 7;
            p_r[j] = *reinterpret_cast<const float4*>(
                ar + (size_t)r * NN + k0 + c4 * 4);
        }
        {
            const int d = tid >> 2, c8 = tid & 3;
            v_r = *reinterpret_cast<const uint4*>(
                vb + (size_t)d * NN + k0 + c8 * 8);
        }
    };
    auto sts_tiles = [&](int st) {
#pragma unroll
        for (int j = 0; j < 4; j++) {
            const int idx = tid * 4 + j;
            const int r = idx >> 3, c4 = idx & 7;
            uint2 u;
            u.x = pack_h2(p_r[j].x, p_r[j].y);
            u.y = pack_h2(p_r[j].z, p_r[j].w);
            *reinterpret_cast<uint2*>(&Ps[st][r][c4 * 4]) = u;
        }
        {
            const int d = tid >> 2, c8 = tid & 3;
            *reinterpret_cast<uint4*>(&Vs[st][d][c8 * 8]) = v_r;
        }
    };

    float acc[2][4][4];
#pragma unroll
    for (int i = 0; i < 2; i++)
#pragma unroll
        for (int j = 0; j < 4; j++)
#pragma unroll
            for (int r = 0; r < 4; r++) acc[i][j][r] = 0.0f;

    const int nIter = NN >> 5;
    ldg_tiles(0);
    sts_tiles(0);
    __syncthreads();
    for (int it = 0; it < nIter; it++) {
        if (it + 1 < nIter) ldg_tiles((it + 1) << 5);
        const int st = it & 1;
#pragma unroll
        for (int ss = 0; ss < 2; ss++) {
            const int kk = ss * 16;
            unsigned a[2][4], bfr[4][2];
#pragma unroll
            for (int i = 0; i < 2; i++)
                ldmx4(a[i][0], a[i][1], a[i][2], a[i][3],
                      &Ps[st][wr * 32 + i * 16 + arow][kk + acol]);
#pragma unroll
            for (int jp = 0; jp < 2; jp++)
                ldmx4(bfr[jp * 2][0], bfr[jp * 2][1],
                      bfr[jp * 2 + 1][0], bfr[jp * 2 + 1][1],
                      &Vs[st][wc * 32 + jp * 16 + brow8][kk + bcol8]);
#pragma unroll
            for (int i = 0; i < 2; i++)
#pragma unroll
                for (int j = 0; j < 4; j++)
                    mma_f16(acc[i][j], a[i][0], a[i][1], a[i][2], a[i][3],
                            bfr[j][0], bfr[j][1]);
        }
        if (it + 1 < nIter) { sts_tiles((it + 1) & 1); __syncthreads(); }
    }

#pragma unroll
    for (int j = 0; j < 4; j++) {
        const int col = h * DD + wc * 32 + j * 8 + 2 * t;
#pragma unroll
        for (int i = 0; i < 2; i++) {
            const int r0 = n0 + wr * 32 + i * 16;
            *reinterpret_cast<unsigned*>(
                &ctxh[((size_t)b * NN + r0 + g) * CC + col]) =
                pack_h2(acc[i][j][0], acc[i][j][1]);
            *reinterpret_cast<unsigned*>(
                &ctxh[((size_t)b * NN + r0 + g + 8) * CC + col]) =
                pack_h2(acc[i][j][2], acc[i][j][3]);
        }
    }
}

// ---------------------------------------------------------------------------
extern "C" void kernel_launch(void* const* d_in, const int* in_sizes, int n_in,
                              void* d_out, int out_size)
{
    (void)in_sizes; (void)n_in; (void)out_size;
    const float* x      = (const float*)d_in[0];
    const float* w_qkv  = (const float*)d_in[1];
    const float* b_qkv  = (const float*)d_in[2];
    const float* w_proj = (const float*)d_in[3];
    const float* b_proj = (const float*)d_in[4];

    float* out  = (float*)d_out;
    float* attn = out + (size_t)BB * NN * CC;

    __half *xh, *qkvh, *ctxh, *wqkvT, *wprojT, *vt;
    cudaGetSymbolAddress((void**)&xh, g_xh);
    cudaGetSymbolAddress((void**)&qkvh, g_qkvh);
    cudaGetSymbolAddress((void**)&ctxh, g_ctxh);
    cudaGetSymbolAddress((void**)&wqkvT, g_wqkvT);
    cudaGetSymbolAddress((void**)&wprojT, g_wprojT);
    cudaGetSymbolAddress((void**)&vt, g_vt);

    const int g_smem = 3 * 256 * 80 + 3 * 128 * 80;   // 92160
    cudaFuncSetAttribute(gemm_h2,
        cudaFuncAttributeMaxDynamicSharedMemorySize, g_smem);

    // 0) One-time conversions
    const int nx8 = BB * NN * CC / 8;
    cvt_f32_h<<<(nx8 + 255) / 256, 256>>>(x, xh, nx8);
    transpose_w_h<<<dim3(CC / 32, 3 * CC / 32), dim3(32, 8)>>>(
        w_qkv, wqkvT, CC, 3 * CC);
    transpose_w_h<<<dim3(CC / 32, CC / 32), dim3(32, 8)>>>(
        w_proj, wprojT, CC, CC);

    // 1) QKV projection (fp16 out)
    gemm_h2<<<dim3(3 * CC / 128, BB * NN / 256), 256, g_smem>>>(
        xh, wqkvT, b_qkv, qkvh, BB * NN, 3 * CC, CC, 1);

    // 1b) V transpose -> [bh][d][m]
    transpose_v_h<<<dim3(NN / 128, BB * HH), 256>>>(qkvh, vt);

    // 2) Fused QK^T + softmax -> attn (single write)
    qk_softmax_h<<<dim3(NN / FROWS, BB * HH), 512>>>(qkvh, attn);

    // 3) attn @ V -> ctx fp16
    av_ctx_h<<<dim3(NN / 128, BB * HH), 256>>>(attn, vt, ctxh);

    // 4) Output projection (fp32 out)
    gemm_h2<<<dim3(CC / 128, BB * NN / 256), 256, g_smem>>>(
        ctxh, wprojT, b_proj, out, BB * NN, CC, CC, 0);
}

// round 12
// speedup vs baseline: 2.9423x; 1.0144x over previous
#include <cuda_runtime.h>
#include <cuda_fp16.h>
#include <cstdint>
#include <cstddef>

// B=8, N=1024, C=1024, H=16, D=64, scale = 0.125
#define BB 8
#define NN 1024
#define CC 1024
#define HH 16
#define DD 64
#define SCALE 0.125f
#define FROWS 32

__device__ __half g_xh[(size_t)BB * NN * CC];
__device__ __half g_qkvh[(size_t)BB * NN * 3 * CC];    // (B,N,3,H,D)
__device__ __half g_ctxh[(size_t)BB * NN * CC];
__device__ __half g_wqkvT[(size_t)3 * CC * CC];        // [n][k]
__device__ __half g_wprojT[(size_t)CC * CC];           // [n][k]
__device__ __half g_vt[(size_t)BB * HH * DD * NN];     // [bh][d][m]

__device__ __forceinline__ unsigned pack_h2(float a, float b) {
    __half2 h = __floats2half2_rn(a, b);
    return *reinterpret_cast<unsigned*>(&h);
}

__device__ __forceinline__ void mma_f16(float c[4],
    unsigned a0, unsigned a1, unsigned a2, unsigned a3,
    unsigned b0, unsigned b1)
{
    asm volatile(
        "mma.sync.aligned.m16n8k16.row.col.f32.f16.f16.f32 "
        "{%0,%1,%2,%3}, {%4,%5,%6,%7}, {%8,%9}, {%0,%1,%2,%3};\n"
        : "+f"(c[0]), "+f"(c[1]), "+f"(c[2]), "+f"(c[3])
        : "r"(a0), "r"(a1), "r"(a2), "r"(a3), "r"(b0), "r"(b1));
}

__device__ __forceinline__ void ldmx4(unsigned& r0, unsigned& r1,
                                      unsigned& r2, unsigned& r3,
                                      const void* p)
{
    unsigned addr = (unsigned)__cvta_generic_to_shared(p);
    asm volatile(
        "ldmatrix.sync.aligned.m8n8.x4.shared.b16 {%0,%1,%2,%3}, [%4];\n"
        : "=r"(r0), "=r"(r1), "=r"(r2), "=r"(r3) : "r"(addr));
}

__device__ __forceinline__ void cp16(void* smem, const void* gmem) {
    unsigned s = (unsigned)__cvta_generic_to_shared(smem);
    asm volatile("cp.async.cg.shared.global [%0], [%1], 16;\n"
                 :: "r"(s), "l"(gmem) : "memory");
}

// ---------------------------------------------------------------------------
__global__ void cvt_f32_h(const float* __restrict__ in,
                          __half* __restrict__ out, int n8)
{
    int i = blockIdx.x * blockDim.x + threadIdx.x;
    if (i >= n8) return;
    const float4* p = reinterpret_cast<const float4*>(in) + (size_t)i * 2;
    float4 v0 = p[0], v1 = p[1];
    uint4 u;
    u.x = pack_h2(v0.x, v0.y);
    u.y = pack_h2(v0.z, v0.w);
    u.z = pack_h2(v1.x, v1.y);
    u.w = pack_h2(v1.z, v1.w);
    reinterpret_cast<uint4*>(out)[i] = u;
}

__global__ void transpose_w_h(const float* __restrict__ W,
                              __half* __restrict__ WT, int K, int N)
{
    __shared__ float tile[32][33];
    const int k0 = blockIdx.x * 32, n0 = blockIdx.y * 32;
    for (int i = threadIdx.y; i < 32; i += 8)
        tile[i][threadIdx.x] = W[(size_t)(k0 + i) * N + n0 + threadIdx.x];
    __syncthreads();
    for (int i = threadIdx.y; i < 32; i += 8)
        WT[(size_t)(n0 + i) * K + k0 + threadIdx.x] =
            __float2half_rn(tile[threadIdx.x][i]);
}

__global__ __launch_bounds__(256) void transpose_v_h(
    const __half* __restrict__ qkvh, __half* __restrict__ vt)
{
    __shared__ __half tile[128][72];
    const int bh = blockIdx.y;
    const int b = bh >> 4, h = bh & 15;
    const int m0 = blockIdx.x * 128;
    const __half* vb = qkvh + (size_t)b * NN * 3 * CC + 2 * CC + h * DD;

#pragma unroll
    for (int it = 0; it < 4; it++) {
        const int idx = threadIdx.x + 256 * it;
        const int m = idx >> 3, c8 = idx & 7;
        uint4 v = *reinterpret_cast<const uint4*>(
            vb + (size_t)(m0 + m) * 3 * CC + c8 * 8);
        *reinterpret_cast<uint4*>(&tile[m][c8 * 8]) = v;
    }
    __syncthreads();
    __half* ob = vt + (size_t)bh * DD * NN + m0;
#pragma unroll
    for (int it = 0; it < 4; it++) {
        const int idx = threadIdx.x + 256 * it;
        const int d = idx >> 4, mc = idx & 15;
        __half hbuf[8];
#pragma unroll
        for (int j = 0; j < 8; j++) hbuf[j] = tile[mc * 8 + j][d];
        *reinterpret_cast<uint4*>(ob + (size_t)d * NN + mc * 8) =
            *reinterpret_cast<uint4*>(hbuf);
    }
}

// ---------------------------------------------------------------------------
// fp16 TC GEMM + bias: C[M,N] = Ah[M,K] @ BT[N,K]^T + bias
// CTA 128x128, 256 thr (8 warps 2x4), warp tile 64x32, BK=32,
// 3-stage cp.async ring (tail-safe wait), 2 CTAs/SM. Dyn smem 61440 B.
// ---------------------------------------------------------------------------
__global__ __launch_bounds__(256, 2) void gemm_h3(
    const __half* __restrict__ Ah, const __half* __restrict__ BT,
    const float* __restrict__ bias, void* __restrict__ Cout,
    int M, int N, int K, int out_half)
{
    extern __shared__ __align__(16) char dsm[];
    char* sA = dsm;                       // 3 stages * 128*80 B
    char* sB = dsm + 3 * 10240;           // 3 stages * 128*80 B

    const int tid  = threadIdx.x;
    const int brow = blockIdx.y * 128;
    const int bcol = blockIdx.x * 128;
    const int w = tid >> 5, l = tid & 31;
    const int wr = w >> 2, wc = w & 3;    // warp: rows wr*64, cols wc*32
    const int g = l >> 2, t = l & 3;

    const int arow = l & 15;
    const int acol = (l >> 4) * 8;
    const int brow8 = ((l >> 4) * 8) + (l & 7);
    const int bcol8 = ((l >> 3) & 1) * 8;

    auto cp_stage = [&](int kc, int st) {
        const int k0 = kc << 5;
#pragma unroll
        for (int j = 0; j < 2; j++) {
            const int i = tid + 256 * j;
            const int r = i >> 2, c = i & 3;
            cp16(sA + st * 10240 + r * 80 + c * 16,
                 Ah + (size_t)(brow + r) * K + k0 + c * 8);
        }
#pragma unroll
        for (int j = 0; j < 2; j++) {
            const int i = tid + 256 * j;
            const int r = i >> 2, c = i & 3;
            cp16(sB + st * 10240 + r * 80 + c * 16,
                 BT + (size_t)(bcol + r) * K + k0 + c * 8);
        }
        asm volatile("cp.async.commit_group;\n" ::: "memory");
    };

    float acc[4][4][4];
#pragma unroll
    for (int i = 0; i < 4; i++)
#pragma unroll
        for (int j = 0; j < 4; j++)
#pragma unroll
            for (int r = 0; r < 4; r++) acc[i][j][r] = 0.0f;

    const int nIter = K >> 5;
    cp_stage(0, 0);
    cp_stage(1, 1);
    for (int it = 0; it < nIter; it++) {
        // Tail-safe wait: the group being consumed MUST be complete.
        if (it + 1 < nIter)
            asm volatile("cp.async.wait_group 1;\n" ::: "memory");
        else
            asm volatile("cp.async.wait_group 0;\n" ::: "memory");
        __syncthreads();
        const int st = it % 3;
        const __half* pA = reinterpret_cast<const __half*>(sA + st * 10240);
        const __half* pB = reinterpret_cast<const __half*>(sB + st * 10240);
#pragma unroll
        for (int ss = 0; ss < 2; ss++) {
            const int kk = ss * 16;
            unsigned a[4][4], b[4][2];
#pragma unroll
            for (int i = 0; i < 4; i++)
                ldmx4(a[i][0], a[i][1], a[i][2], a[i][3],
                      pA + (wr * 64 + i * 16 + arow) * 40 + kk + acol);
#pragma unroll
            for (int jp = 0; jp < 2; jp++)
                ldmx4(b[jp * 2][0], b[jp * 2][1],
                      b[jp * 2 + 1][0], b[jp * 2 + 1][1],
                      pB + (wc * 32 + jp * 16 + brow8) * 40 + kk + bcol8);
#pragma unroll
            for (int i = 0; i < 4; i++)
#pragma unroll
                for (int j = 0; j < 4; j++)
                    mma_f16(acc[i][j], a[i][0], a[i][1], a[i][2], a[i][3],
                            b[j][0], b[j][1]);
        }
        if (it + 2 < nIter) cp_stage(it + 2, (it + 2) % 3);
    }

    if (out_half) {
        __half* C = reinterpret_cast<__half*>(Cout);
#pragma unroll
        for (int j = 0; j < 4; j++) {
            const int col = bcol + wc * 32 + j * 8 + 2 * t;
            const float b0 = bias[col], b1 = bias[col + 1];
#pragma unroll
            for (int i = 0; i < 4; i++) {
                const int r0 = brow + wr * 64 + i * 16;
                *reinterpret_cast<unsigned*>(&C[(size_t)(r0 + g) * N + col]) =
                    pack_h2(acc[i][j][0] + b0, acc[i][j][1] + b1);
                *reinterpret_cast<unsigned*>(&C[(size_t)(r0 + g + 8) * N + col]) =
                    pack_h2(acc[i][j][2] + b0, acc[i][j][3] + b1);
            }
        }
    } else {
        float* C = reinterpret_cast<float*>(Cout);
#pragma unroll
        for (int j = 0; j < 4; j++) {
            const int col = bcol + wc * 32 + j * 8 + 2 * t;
            const float b0 = bias[col], b1 = bias[col + 1];
#pragma unroll
            for (int i = 0; i < 4; i++) {
                const int r0 = brow + wr * 64 + i * 16;
                float2 o0 = {acc[i][j][0] + b0, acc[i][j][1] + b1};
                float2 o1 = {acc[i][j][2] + b0, acc[i][j][3] + b1};
                *reinterpret_cast<float2*>(&C[(size_t)(r0 + g) * N + col]) = o0;
                *reinterpret_cast<float2*>(&C[(size_t)(r0 + g + 8) * N + col]) = o1;
            }
        }
    }
}

// ---------------------------------------------------------------------------
// Fused QK^T + softmax. 32 rows x 1024 keys per block, 512 threads.
// K streamed via 3-stage cp.async ring (tail-safe); Q frags in registers.
// ---------------------------------------------------------------------------
__global__ __launch_bounds__(512) void qk_softmax_h(
    const __half* __restrict__ qkvh, float* __restrict__ attn)
{
    __shared__ __align__(16) __half Qs[32][72];
    __shared__ __align__(16) __half Ks[3][128][72];
    __shared__ float redM[32 * 9];
    __shared__ float redS[32 * 9];

    const int bh = blockIdx.y;
    const int b = bh >> 4, h = bh & 15;
    const int n0 = blockIdx.x * FROWS;

    const int tid = threadIdx.x;
    const int w = tid >> 5, l = tid & 31;
    const int g = l >> 2, t = l & 3;
    const int wr = w >> 3, wc = w & 7;

    const int arow = l & 15;
    const int acol = (l >> 4) * 8;
    const int brow8 = ((l >> 4) * 8) + (l & 7);
    const int bcol8 = ((l >> 3) & 1) * 8;

    const __half* qb = qkvh + (size_t)b * NN * 3 * CC + h * DD;
    const __half* kb = qb + CC;

    auto cp_k = [&](int c, int st) {
        const int m0 = c * 128;
#pragma unroll
        for (int j = 0; j < 2; j++) {
            const int idx = tid * 2 + j;
            const int m = idx >> 3, c8 = idx & 7;
            cp16(&Ks[st][m][c8 * 8], kb + (size_t)(m0 + m) * 3 * CC + c8 * 8);
        }
        asm volatile("cp.async.commit_group;\n" ::: "memory");
    };

    cp_k(0, 0);
    cp_k(1, 1);

    if (tid < 256) {
        const int row = tid >> 3, c8 = tid & 7;
        *reinterpret_cast<uint4*>(&Qs[row][c8 * 8]) =
            *reinterpret_cast<const uint4*>(qb + (size_t)(n0 + row) * 3 * CC + c8 * 8);
    }
    __syncthreads();

    unsigned qa[4][4];
#pragma unroll
    for (int ss = 0; ss < 4; ss++)
        ldmx4(qa[ss][0], qa[ss][1], qa[ss][2], qa[ss][3],
              &Qs[wr * 16 + arow][ss * 16 + acol]);

    float acc[8][2][4];
#pragma unroll
    for (int c = 0; c < 8; c++)
#pragma unroll
        for (int jn = 0; jn < 2; jn++)
#pragma unroll
            for (int r = 0; r < 4; r++) acc[c][jn][r] = 0.0f;

    const int row0 = wr * 16 + g;
    const int row1 = row0 + 8;

#pragma unroll
    for (int c = 0; c < 8; c++) {
        // Tail-safe wait (c is compile-time constant after unroll)
        if (c + 1 < 8)
            asm volatile("cp.async.wait_group 1;\n" ::: "memory");
        else
            asm volatile("cp.async.wait_group 0;\n" ::: "memory");
        __syncthreads();
        const int st = c % 3;
#pragma unroll
        for (int ss = 0; ss < 4; ss++) {
            const int kk = ss * 16;
            unsigned kb0, kb1, kb2, kb3;
            ldmx4(kb0, kb1, kb2, kb3,
                  &Ks[st][wc * 16 + brow8][kk + bcol8]);
            mma_f16(acc[c][0], qa[ss][0], qa[ss][1], qa[ss][2], qa[ss][3], kb0, kb1);
            mma_f16(acc[c][1], qa[ss][0], qa[ss][1], qa[ss][2], qa[ss][3], kb2, kb3);
        }
        if (c + 2 < 8) cp_k(c + 2, (c + 2) % 3);
    }

#pragma unroll
    for (int c = 0; c < 8; c++)
#pragma unroll
        for (int jn = 0; jn < 2; jn++)
#pragma unroll
            for (int r = 0; r < 4; r++) acc[c][jn][r] *= SCALE;

    float mx0 = -3.402823466e+38f, mx1 = -3.402823466e+38f;
#pragma unroll
    for (int c = 0; c < 8; c++)
#pragma unroll
        for (int jn = 0; jn < 2; jn++) {
            mx0 = fmaxf(mx0, fmaxf(acc[c][jn][0], acc[c][jn][1]));
            mx1 = fmaxf(mx1, fmaxf(acc[c][jn][2], acc[c][jn][3]));
        }
#pragma unroll
    for (int o = 1; o <= 2; o <<= 1) {
        mx0 = fmaxf(mx0, __shfl_xor_sync(0xffffffffu, mx0, o));
        mx1 = fmaxf(mx1, __shfl_xor_sync(0xffffffffu, mx1, o));
    }
    if (t == 0) {
        redM[row0 * 9 + wc] = mx0;
        redM[row1 * 9 + wc] = mx1;
    }
    __syncthreads();
    mx0 = redM[row0 * 9];
    mx1 = redM[row1 * 9];
#pragma unroll
    for (int k = 1; k < 8; k++) {
        mx0 = fmaxf(mx0, redM[row0 * 9 + k]);
        mx1 = fmaxf(mx1, redM[row1 * 9 + k]);
    }

    float s0 = 0.0f, s1 = 0.0f;
#pragma unroll
    for (int c = 0; c < 8; c++)
#pragma unroll
        for (int jn = 0; jn < 2; jn++) {
            acc[c][jn][0] = __expf(acc[c][jn][0] - mx0);
            acc[c][jn][1] = __expf(acc[c][jn][1] - mx0);
            acc[c][jn][2] = __expf(acc[c][jn][2] - mx1);
            acc[c][jn][3] = __expf(acc[c][jn][3] - mx1);
            s0 += acc[c][jn][0] + acc[c][jn][1];
            s1 += acc[c][jn][2] + acc[c][jn][3];
        }
#pragma unroll
    for (int o = 1; o <= 2; o <<= 1) {
        s0 += __shfl_xor_sync(0xffffffffu, s0, o);
        s1 += __shfl_xor_sync(0xffffffffu, s1, o);
    }
    if (t == 0) {
        redS[row0 * 9 + wc] = s0;
        redS[row1 * 9 + wc] = s1;
    }
    __syncthreads();
    s0 = redS[row0 * 9];
    s1 = redS[row1 * 9];
#pragma unroll
    for (int k = 1; k < 8; k++) {
        s0 += redS[row0 * 9 + k];
        s1 += redS[row1 * 9 + k];
    }
    const float inv0 = 1.0f / s0;
    const float inv1 = 1.0f / s1;

    float* arow0 = attn + ((size_t)bh * NN + n0 + row0) * NN;
    float* arow1 = attn + ((size_t)bh * NN + n0 + row1) * NN;
#pragma unroll
    for (int c = 0; c < 8; c++)
#pragma unroll
        for (int jn = 0; jn < 2; jn++) {
            const int col = c * 128 + wc * 16 + jn * 8 + 2 * t;
            float2 o0 = {acc[c][jn][0] * inv0, acc[c][jn][1] * inv0};
            float2 o1 = {acc[c][jn][2] * inv1, acc[c][jn][3] * inv1};
            *reinterpret_cast<float2*>(&arow0[col]) = o0;
            *reinterpret_cast<float2*>(&arow1[col]) = o1;
        }
}

// ---------------------------------------------------------------------------
// PV (fp16 mma + ldmatrix), 2 CTAs/SM. Synchronous double buffer (no cp.async).
// ---------------------------------------------------------------------------
__global__ __launch_bounds__(256, 2) void av_ctx_h(
    const float* __restrict__ attn, const __half* __restrict__ vt,
    __half* __restrict__ ctxh)
{
    __shared__ __align__(16) __half Ps[2][128][40];
    __shared__ __align__(16) __half Vs[2][64][40];

    const int bh = blockIdx.y;
    const int b = bh >> 4, h = bh & 15;
    const int n0 = blockIdx.x * 128;

    const float* ar = attn + ((size_t)bh * NN + n0) * NN;
    const __half* vb = vt + (size_t)bh * DD * NN;

    const int tid = threadIdx.x;
    const int w = tid >> 5, l = tid & 31;
    const int wr = w >> 1, wc = w & 1;
    const int g = l >> 2, t = l & 3;

    const int arow = l & 15;
    const int acol = (l >> 4) * 8;
    const int brow8 = ((l >> 4) * 8) + (l & 7);
    const int bcol8 = ((l >> 3) & 1) * 8;

    float4 p_r[4];
    uint4 v_r;
    auto ldg_tiles = [&](int k0) {
#pragma unroll
        for (int j = 0; j < 4; j++) {
            const int idx = tid * 4 + j;
            const int r = idx >> 3, c4 = idx & 7;
            p_r[j] = *reinterpret_cast<const float4*>(
                ar + (size_t)r * NN + k0 + c4 * 4);
        }
        {
            const int d = tid >> 2, c8 = tid & 3;
            v_r = *reinterpret_cast<const uint4*>(
                vb + (size_t)d * NN + k0 + c8 * 8);
        }
    };
    auto sts_tiles = [&](int st) {
#pragma unroll
        for (int j = 0; j < 4; j++) {
            const int idx = tid * 4 + j;
            const int r = idx >> 3, c4 = idx & 7;
            uint2 u;
            u.x = pack_h2(p_r[j].x, p_r[j].y);
            u.y = pack_h2(p_r[j].z, p_r[j].w);
            *reinterpret_cast<uint2*>(&Ps[st][r][c4 * 4]) = u;
        }
        {
            const int d = tid >> 2, c8 = tid & 3;
            *reinterpret_cast<uint4*>(&Vs[st][d][c8 * 8]) = v_r;
        }
    };

    float acc[2][4][4];
#pragma unroll
    for (int i = 0; i < 2; i++)
#pragma unroll
        for (int j = 0; j < 4; j++)
#pragma unroll
            for (int r = 0; r < 4; r++) acc[i][j][r] = 0.0f;

    const int nIter = NN >> 5;
    ldg_tiles(0);
    sts_tiles(0);
    __syncthreads();
    for (int it = 0; it < nIter; it++) {
        if (it + 1 < nIter) ldg_tiles((it + 1) << 5);
        const int st = it & 1;
#pragma unroll
        for (int ss = 0; ss < 2; ss++) {
            const int kk = ss * 16;
            unsigned a[2][4], bfr[4][2];
#pragma unroll
            for (int i = 0; i < 2; i++)
                ldmx4(a[i][0], a[i][1], a[i][2], a[i][3],
                      &Ps[st][wr * 32 + i * 16 + arow][kk + acol]);
#pragma unroll
            for (int jp = 0; jp < 2; jp++)
                ldmx4(bfr[jp * 2][0], bfr[jp * 2][1],
                      bfr[jp * 2 + 1][0], bfr[jp * 2 + 1][1],
                      &Vs[st][wc * 32 + jp * 16 + brow8][kk + bcol8]);
#pragma unroll
            for (int i = 0; i < 2; i++)
#pragma unroll
                for (int j = 0; j < 4; j++)
                    mma_f16(acc[i][j], a[i][0], a[i][1], a[i][2], a[i][3],
                            bfr[j][0], bfr[j][1]);
        }
        if (it + 1 < nIter) { sts_tiles((it + 1) & 1); __syncthreads(); }
    }

#pragma unroll
    for (int j = 0; j < 4; j++) {
        const int col = h * DD + wc * 32 + j * 8 + 2 * t;
#pragma unroll
        for (int i = 0; i < 2; i++) {
            const int r0 = n0 + wr * 32 + i * 16;
            *reinterpret_cast<unsigned*>(
                &ctxh[((size_t)b * NN + r0 + g) * CC + col]) =
                pack_h2(acc[i][j][0], acc[i][j][1]);
            *reinterpret_cast<unsigned*>(
                &ctxh[((size_t)b * NN + r0 + g + 8) * CC + col]) =
                pack_h2(acc[i][j][2], acc[i][j][3]);
        }
    }
}

// ---------------------------------------------------------------------------
extern "C" void kernel_launch(void* const* d_in, const int* in_sizes, int n_in,
                              void* d_out, int out_size)
{
    (void)in_sizes; (void)n_in; (void)out_size;
    const float* x      = (const float*)d_in[0];
    const float* w_qkv  = (const float*)d_in[1];
    const float* b_qkv  = (const float*)d_in[2];
    const float* w_proj = (const float*)d_in[3];
    const float* b_proj = (const float*)d_in[4];

    float* out  = (float*)d_out;
    float* attn = out + (size_t)BB * NN * CC;

    __half *xh, *qkvh, *ctxh, *wqkvT, *wprojT, *vt;
    cudaGetSymbolAddress((void**)&xh, g_xh);
    cudaGetSymbolAddress((void**)&qkvh, g_qkvh);
    cudaGetSymbolAddress((void**)&ctxh, g_ctxh);
    cudaGetSymbolAddress((void**)&wqkvT, g_wqkvT);
    cudaGetSymbolAddress((void**)&wprojT, g_wprojT);
    cudaGetSymbolAddress((void**)&vt, g_vt);

    const int g_smem = 6 * 10240;   // 61440
    cudaFuncSetAttribute(gemm_h3,
        cudaFuncAttributeMaxDynamicSharedMemorySize, g_smem);

    // 0) One-time conversions
    const int nx8 = BB * NN * CC / 8;
    cvt_f32_h<<<(nx8 + 255) / 256, 256>>>(x, xh, nx8);
    transpose_w_h<<<dim3(CC / 32, 3 * CC / 32), dim3(32, 8)>>>(
        w_qkv, wqkvT, CC, 3 * CC);
    transpose_w_h<<<dim3(CC / 32, CC / 32), dim3(32, 8)>>>(
        w_proj, wprojT, CC, CC);

    // 1) QKV projection (fp16 out)
    gemm_h3<<<dim3(3 * CC / 128, BB * NN / 128), 256, g_smem>>>(
        xh, wqkvT, b_qkv, qkvh, BB * NN, 3 * CC, CC, 1);

    // 1b) V transpose -> [bh][d][m]
    transpose_v_h<<<dim3(NN / 128, BB * HH), 256>>>(qkvh, vt);

    // 2) Fused QK^T + softmax -> attn (single write)
    qk_softmax_h<<<dim3(NN / FROWS, BB * HH), 512>>>(qkvh, attn);

    // 3) attn @ V -> ctx fp16
    av_ctx_h<<<dim3(NN / 128, BB * HH), 256>>>(attn, vt, ctxh);

    // 4) Output projection (fp32 out)
    gemm_h3<<<dim3(CC / 128, BB * NN / 128), 256, g_smem>>>(
        ctxh, wprojT, b_proj, out, BB * NN, CC, CC, 0);
}

// round 13
// speedup vs baseline: 3.0488x; 1.0362x over previous
#include <cuda_runtime.h>
#include <cuda_fp16.h>
#include <cstdint>
#include <cstddef>

// B=8, N=1024, C=1024, H=16, D=64, scale = 0.125
#define BB 8
#define NN 1024
#define CC 1024
#define HH 16
#define DD 64
#define SCALE 0.125f
#define FROWS 32

__device__ __half g_xh[(size_t)BB * NN * CC];
__device__ __half g_qkvh[(size_t)BB * NN * 3 * CC];    // (B,N,3,H,D)
__device__ __half g_ctxh[(size_t)BB * NN * CC];
__device__ __half g_wqkvT[(size_t)3 * CC * CC];        // [n][k]
__device__ __half g_wprojT[(size_t)CC * CC];           // [n][k]
__device__ __half g_vt[(size_t)BB * HH * DD * NN];     // [bh][d][m]

__device__ __forceinline__ unsigned pack_h2(float a, float b) {
    __half2 h = __floats2half2_rn(a, b);
    return *reinterpret_cast<unsigned*>(&h);
}

__device__ __forceinline__ void mma_f16(float c[4],
    unsigned a0, unsigned a1, unsigned a2, unsigned a3,
    unsigned b0, unsigned b1)
{
    asm volatile(
        "mma.sync.aligned.m16n8k16.row.col.f32.f16.f16.f32 "
        "{%0,%1,%2,%3}, {%4,%5,%6,%7}, {%8,%9}, {%0,%1,%2,%3};\n"
        : "+f"(c[0]), "+f"(c[1]), "+f"(c[2]), "+f"(c[3])
        : "r"(a0), "r"(a1), "r"(a2), "r"(a3), "r"(b0), "r"(b1));
}

__device__ __forceinline__ void ldmx4(unsigned& r0, unsigned& r1,
                                      unsigned& r2, unsigned& r3,
                                      const void* p)
{
    unsigned addr = (unsigned)__cvta_generic_to_shared(p);
    asm volatile(
        "ldmatrix.sync.aligned.m8n8.x4.shared.b16 {%0,%1,%2,%3}, [%4];\n"
        : "=r"(r0), "=r"(r1), "=r"(r2), "=r"(r3) : "r"(addr));
}

__device__ __forceinline__ void cp16(void* smem, const void* gmem) {
    unsigned s = (unsigned)__cvta_generic_to_shared(smem);
    asm volatile("cp.async.cg.shared.global [%0], [%1], 16;\n"
                 :: "r"(s), "l"(gmem) : "memory");
}

// ---------------------------------------------------------------------------
__global__ void cvt_f32_h(const float* __restrict__ in,
                          __half* __restrict__ out, int n8)
{
    int i = blockIdx.x * blockDim.x + threadIdx.x;
    if (i >= n8) return;
    const float4* p = reinterpret_cast<const float4*>(in) + (size_t)i * 2;
    float4 v0 = p[0], v1 = p[1];
    uint4 u;
    u.x = pack_h2(v0.x, v0.y);
    u.y = pack_h2(v0.z, v0.w);
    u.z = pack_h2(v1.x, v1.y);
    u.w = pack_h2(v1.z, v1.w);
    reinterpret_cast<uint4*>(out)[i] = u;
}

__global__ void transpose_w_h(const float* __restrict__ W,
                              __half* __restrict__ WT, int K, int N)
{
    __shared__ float tile[32][33];
    const int k0 = blockIdx.x * 32, n0 = blockIdx.y * 32;
    for (int i = threadIdx.y; i < 32; i += 8)
        tile[i][threadIdx.x] = W[(size_t)(k0 + i) * N + n0 + threadIdx.x];
    __syncthreads();
    for (int i = threadIdx.y; i < 32; i += 8)
        WT[(size_t)(n0 + i) * K + k0 + threadIdx.x] =
            __float2half_rn(tile[threadIdx.x][i]);
}

__global__ __launch_bounds__(256) void transpose_v_h(
    const __half* __restrict__ qkvh, __half* __restrict__ vt)
{
    __shared__ __half tile[128][72];
    const int bh = blockIdx.y;
    const int b = bh >> 4, h = bh & 15;
    const int m0 = blockIdx.x * 128;
    const __half* vb = qkvh + (size_t)b * NN * 3 * CC + 2 * CC + h * DD;

#pragma unroll
    for (int it = 0; it < 4; it++) {
        const int idx = threadIdx.x + 256 * it;
        const int m = idx >> 3, c8 = idx & 7;
        uint4 v = *reinterpret_cast<const uint4*>(
            vb + (size_t)(m0 + m) * 3 * CC + c8 * 8);
        *reinterpret_cast<uint4*>(&tile[m][c8 * 8]) = v;
    }
    __syncthreads();
    __half* ob = vt + (size_t)bh * DD * NN + m0;
#pragma unroll
    for (int it = 0; it < 4; it++) {
        const int idx = threadIdx.x + 256 * it;
        const int d = idx >> 4, mc = idx & 15;
        __half hbuf[8];
#pragma unroll
        for (int j = 0; j < 8; j++) hbuf[j] = tile[mc * 8 + j][d];
        *reinterpret_cast<uint4*>(ob + (size_t)d * NN + mc * 8) =
            *reinterpret_cast<uint4*>(hbuf);
    }
}

// ---------------------------------------------------------------------------
// fp16 TC GEMM + bias (unchanged from R12, tail-safe cp.async ring).
// ---------------------------------------------------------------------------
__global__ __launch_bounds__(256, 2) void gemm_h3(
    const __half* __restrict__ Ah, const __half* __restrict__ BT,
    const float* __restrict__ bias, void* __restrict__ Cout,
    int M, int N, int K, int out_half)
{
    extern __shared__ __align__(16) char dsm[];
    char* sA = dsm;
    char* sB = dsm + 3 * 10240;

    const int tid  = threadIdx.x;
    const int brow = blockIdx.y * 128;
    const int bcol = blockIdx.x * 128;
    const int w = tid >> 5, l = tid & 31;
    const int wr = w >> 2, wc = w & 3;
    const int g = l >> 2, t = l & 3;

    const int arow = l & 15;
    const int acol = (l >> 4) * 8;
    const int brow8 = ((l >> 4) * 8) + (l & 7);
    const int bcol8 = ((l >> 3) & 1) * 8;

    auto cp_stage = [&](int kc, int st) {
        const int k0 = kc << 5;
#pragma unroll
        for (int j = 0; j < 2; j++) {
            const int i = tid + 256 * j;
            const int r = i >> 2, c = i & 3;
            cp16(sA + st * 10240 + r * 80 + c * 16,
                 Ah + (size_t)(brow + r) * K + k0 + c * 8);
        }
#pragma unroll
        for (int j = 0; j < 2; j++) {
            const int i = tid + 256 * j;
            const int r = i >> 2, c = i & 3;
            cp16(sB + st * 10240 + r * 80 + c * 16,
                 BT + (size_t)(bcol + r) * K + k0 + c * 8);
        }
        asm volatile("cp.async.commit_group;\n" ::: "memory");
    };

    float acc[4][4][4];
#pragma unroll
    for (int i = 0; i < 4; i++)
#pragma unroll
        for (int j = 0; j < 4; j++)
#pragma unroll
            for (int r = 0; r < 4; r++) acc[i][j][r] = 0.0f;

    const int nIter = K >> 5;
    cp_stage(0, 0);
    cp_stage(1, 1);
    for (int it = 0; it < nIter; it++) {
        if (it + 1 < nIter)
            asm volatile("cp.async.wait_group 1;\n" ::: "memory");
        else
            asm volatile("cp.async.wait_group 0;\n" ::: "memory");
        __syncthreads();
        const int st = it % 3;
        const __half* pA = reinterpret_cast<const __half*>(sA + st * 10240);
        const __half* pB = reinterpret_cast<const __half*>(sB + st * 10240);
#pragma unroll
        for (int ss = 0; ss < 2; ss++) {
            const int kk = ss * 16;
            unsigned a[4][4], b[4][2];
#pragma unroll
            for (int i = 0; i < 4; i++)
                ldmx4(a[i][0], a[i][1], a[i][2], a[i][3],
                      pA + (wr * 64 + i * 16 + arow) * 40 + kk + acol);
#pragma unroll
            for (int jp = 0; jp < 2; jp++)
                ldmx4(b[jp * 2][0], b[jp * 2][1],
                      b[jp * 2 + 1][0], b[jp * 2 + 1][1],
                      pB + (wc * 32 + jp * 16 + brow8) * 40 + kk + bcol8);
#pragma unroll
            for (int i = 0; i < 4; i++)
#pragma unroll
                for (int j = 0; j < 4; j++)
                    mma_f16(acc[i][j], a[i][0], a[i][1], a[i][2], a[i][3],
                            b[j][0], b[j][1]);
        }
        if (it + 2 < nIter) cp_stage(it + 2, (it + 2) % 3);
    }

    if (out_half) {
        __half* C = reinterpret_cast<__half*>(Cout);
#pragma unroll
        for (int j = 0; j < 4; j++) {
            const int col = bcol + wc * 32 + j * 8 + 2 * t;
            const float b0 = bias[col], b1 = bias[col + 1];
#pragma unroll
            for (int i = 0; i < 4; i++) {
                const int r0 = brow + wr * 64 + i * 16;
                *reinterpret_cast<unsigned*>(&C[(size_t)(r0 + g) * N + col]) =
                    pack_h2(acc[i][j][0] + b0, acc[i][j][1] + b1);
                *reinterpret_cast<unsigned*>(&C[(size_t)(r0 + g + 8) * N + col]) =
                    pack_h2(acc[i][j][2] + b0, acc[i][j][3] + b1);
            }
        }
    } else {
        float* C = reinterpret_cast<float*>(Cout);
#pragma unroll
        for (int j = 0; j < 4; j++) {
            const int col = bcol + wc * 32 + j * 8 + 2 * t;
            const float b0 = bias[col], b1 = bias[col + 1];
#pragma unroll
            for (int i = 0; i < 4; i++) {
                const int r0 = brow + wr * 64 + i * 16;
                float2 o0 = {acc[i][j][0] + b0, acc[i][j][1] + b1};
                float2 o1 = {acc[i][j][2] + b0, acc[i][j][3] + b1};
                *reinterpret_cast<float2*>(&C[(size_t)(r0 + g) * N + col]) = o0;
                *reinterpret_cast<float2*>(&C[(size_t)(r0 + g + 8) * N + col]) = o1;
            }
        }
    }
}

// ---------------------------------------------------------------------------
// Fully fused attention: QK^T -> softmax -> attn write -> PV -> ctx write.
// Block: 32 rows x 1024 keys of one (b,h). 512 threads, 16 warps (wr 2 x wc 8).
// P stays in registers end-to-end; V streamed through smem freed by K ring.
// Dyn smem (reused across phases):
//   QK:  Qs[32][72] | Ks[3][128][72]          = 59904 B
//   PV:  Vs[2][64][136]                        = 34816 B
//   red: float4 buf [8 areas][8][32]           = 32768 B
// ---------------------------------------------------------------------------
__global__ __launch_bounds__(512) void attn_fused_h(
    const __half* __restrict__ qkvh, const __half* __restrict__ vt,
    float* __restrict__ attn, __half* __restrict__ ctxh)
{
    extern __shared__ __align__(16) char dyn[];
    __half* Qs = reinterpret_cast<__half*>(dyn);            // [32][72]
    __half* Ks = Qs + 32 * 72;                              // [3][128][72]
    __half* Vs = reinterpret_cast<__half*>(dyn);            // [2][64][136]
    float4* redO = reinterpret_cast<float4*>(dyn);          // [8][8][32]
    __shared__ float redM[32 * 9];
    __shared__ float redS[32 * 9];

    const int bh = blockIdx.y;
    const int b = bh >> 4, h = bh & 15;
    const int n0 = blockIdx.x * FROWS;

    const int tid = threadIdx.x;
    const int w = tid >> 5, l = tid & 31;
    const int g = l >> 2, t = l & 3;
    const int wr = w >> 3, wc = w & 7;

    const int arow = l & 15;
    const int acol = (l >> 4) * 8;
    const int brow8 = ((l >> 4) * 8) + (l & 7);
    const int bcol8 = ((l >> 3) & 1) * 8;

    const __half* qb = qkvh + (size_t)b * NN * 3 * CC + h * DD;
    const __half* kb = qb + CC;
    const __half* vb = vt + (size_t)bh * DD * NN;

    // ---------------- Phase 1: QK^T ----------------
    auto cp_k = [&](int c, int st) {
        const int m0 = c * 128;
#pragma unroll
        for (int j = 0; j < 2; j++) {
            const int idx = tid * 2 + j;
            const int m = idx >> 3, c8 = idx & 7;
            cp16(Ks + (st * 128 + m) * 72 + c8 * 8,
                 kb + (size_t)(m0 + m) * 3 * CC + c8 * 8);
        }
        asm volatile("cp.async.commit_group;\n" ::: "memory");
    };

    cp_k(0, 0);
    cp_k(1, 1);

    if (tid < 256) {
        const int row = tid >> 3, c8 = tid & 7;
        *reinterpret_cast<uint4*>(Qs + row * 72 + c8 * 8) =
            *reinterpret_cast<const uint4*>(qb + (size_t)(n0 + row) * 3 * CC + c8 * 8);
    }
    __syncthreads();

    unsigned qa[4][4];
#pragma unroll
    for (int ss = 0; ss < 4; ss++)
        ldmx4(qa[ss][0], qa[ss][1], qa[ss][2], qa[ss][3],
              Qs + (wr * 16 + arow) * 72 + ss * 16 + acol);

    float acc[8][2][4];
#pragma unroll
    for (int c = 0; c < 8; c++)
#pragma unroll
        for (int jn = 0; jn < 2; jn++)
#pragma unroll
            for (int r = 0; r < 4; r++) acc[c][jn][r] = 0.0f;

    const int row0 = wr * 16 + g;
    const int row1 = row0 + 8;

#pragma unroll
    for (int c = 0; c < 8; c++) {
        if (c + 1 < 8)
            asm volatile("cp.async.wait_group 1;\n" ::: "memory");
        else
            asm volatile("cp.async.wait_group 0;\n" ::: "memory");
        __syncthreads();
        const int st = c % 3;
#pragma unroll
        for (int ss = 0; ss < 4; ss++) {
            const int kk = ss * 16;
            unsigned kb0, kb1, kb2, kb3;
            ldmx4(kb0, kb1, kb2, kb3,
                  Ks + (st * 128 + wc * 16 + brow8) * 72 + kk + bcol8);
            mma_f16(acc[c][0], qa[ss][0], qa[ss][1], qa[ss][2], qa[ss][3], kb0, kb1);
            mma_f16(acc[c][1], qa[ss][0], qa[ss][1], qa[ss][2], qa[ss][3], kb2, kb3);
        }
        if (c + 2 < 8) cp_k(c + 2, (c + 2) % 3);
    }

    // ---------------- Phase 2: softmax ----------------
#pragma unroll
    for (int c = 0; c < 8; c++)
#pragma unroll
        for (int jn = 0; jn < 2; jn++)
#pragma unroll
            for (int r = 0; r < 4; r++) acc[c][jn][r] *= SCALE;

    float mx0 = -3.402823466e+38f, mx1 = -3.402823466e+38f;
#pragma unroll
    for (int c = 0; c < 8; c++)
#pragma unroll
        for (int jn = 0; jn < 2; jn++) {
            mx0 = fmaxf(mx0, fmaxf(acc[c][jn][0], acc[c][jn][1]));
            mx1 = fmaxf(mx1, fmaxf(acc[c][jn][2], acc[c][jn][3]));
        }
#pragma unroll
    for (int o = 1; o <= 2; o <<= 1) {
        mx0 = fmaxf(mx0, __shfl_xor_sync(0xffffffffu, mx0, o));
        mx1 = fmaxf(mx1, __shfl_xor_sync(0xffffffffu, mx1, o));
    }
    if (t == 0) {
        redM[row0 * 9 + wc] = mx0;
        redM[row1 * 9 + wc] = mx1;
    }
    __syncthreads();
    mx0 = redM[row0 * 9];
    mx1 = redM[row1 * 9];
#pragma unroll
    for (int k = 1; k < 8; k++) {
        mx0 = fmaxf(mx0, redM[row0 * 9 + k]);
        mx1 = fmaxf(mx1, redM[row1 * 9 + k]);
    }

    float s0 = 0.0f, s1 = 0.0f;
#pragma unroll
    for (int c = 0; c < 8; c++)
#pragma unroll
        for (int jn = 0; jn < 2; jn++) {
            acc[c][jn][0] = __expf(acc[c][jn][0] - mx0);
            acc[c][jn][1] = __expf(acc[c][jn][1] - mx0);
            acc[c][jn][2] = __expf(acc[c][jn][2] - mx1);
            acc[c][jn][3] = __expf(acc[c][jn][3] - mx1);
            s0 += acc[c][jn][0] + acc[c][jn][1];
            s1 += acc[c][jn][2] + acc[c][jn][3];
        }
#pragma unroll
    for (int o = 1; o <= 2; o <<= 1) {
        s0 += __shfl_xor_sync(0xffffffffu, s0, o);
        s1 += __shfl_xor_sync(0xffffffffu, s1, o);
    }
    if (t == 0) {
        redS[row0 * 9 + wc] = s0;
        redS[row1 * 9 + wc] = s1;
    }
    __syncthreads();
    s0 = redS[row0 * 9];
    s1 = redS[row1 * 9];
#pragma unroll
    for (int k = 1; k < 8; k++) {
        s0 += redS[row0 * 9 + k];
        s1 += redS[row1 * 9 + k];
    }
    const float inv0 = 1.0f / s0;
    const float inv1 = 1.0f / s1;

#pragma unroll
    for (int c = 0; c < 8; c++)
#pragma unroll
        for (int jn = 0; jn < 2; jn++) {
            acc[c][jn][0] *= inv0;
            acc[c][jn][1] *= inv0;
            acc[c][jn][2] *= inv1;
            acc[c][jn][3] *= inv1;
        }

    // ---------------- Phase 3: write attn (single pass) ----------------
    {
        float* arow0 = attn + ((size_t)bh * NN + n0 + row0) * NN;
        float* arow1 = attn + ((size_t)bh * NN + n0 + row1) * NN;
#pragma unroll
        for (int c = 0; c < 8; c++)
#pragma unroll
            for (int jn = 0; jn < 2; jn++) {
                const int col = c * 128 + wc * 16 + jn * 8 + 2 * t;
                float2 o0 = {acc[c][jn][0], acc[c][jn][1]};
                float2 o1 = {acc[c][jn][2], acc[c][jn][3]};
                *reinterpret_cast<float2*>(&arow0[col]) = o0;
                *reinterpret_cast<float2*>(&arow1[col]) = o1;
            }
    }

    // ---------------- Phase 4: PV (P frags from registers) ----------------
    // P A-fragments per k16-slab c (keys c*128 + wc*16 .. +15):
    //   a0=P[g][2t], a1=P[g+8][2t], a2=P[g][2t+8], a3=P[g+8][2t+8]
    float oacc[8][4];
#pragma unroll
    for (int j = 0; j < 8; j++)
#pragma unroll
        for (int r = 0; r < 4; r++) oacc[j][r] = 0.0f;

    uint4 vpre[2];
    auto ldg_v = [&](int c) {
#pragma unroll
        for (int j = 0; j < 2; j++) {
            const int idx = tid + 512 * j;
            const int d = idx >> 4, k8 = idx & 15;
            vpre[j] = *reinterpret_cast<const uint4*>(
                vb + (size_t)d * NN + c * 128 + k8 * 8);
        }
    };
    auto sts_v = [&](int st) {
#pragma unroll
        for (int j = 0; j < 2; j++) {
            const int idx = tid + 512 * j;
            const int d = idx >> 4, k8 = idx & 15;
            *reinterpret_cast<uint4*>(Vs + (st * 64 + d) * 136 + k8 * 8) = vpre[j];
        }
    };

    __syncthreads();    // all QK smem reads done; Vs overlays Qs/Ks
    ldg_v(0);
    sts_v(0);
    __syncthreads();
#pragma unroll
    for (int c = 0; c < 8; c++) {
        if (c + 1 < 8) ldg_v(c + 1);
        const int st = c & 1;
        const unsigned pa0 = pack_h2(acc[c][0][0], acc[c][0][1]);
        const unsigned pa1 = pack_h2(acc[c][0][2], acc[c][0][3]);
        const unsigned pa2 = pack_h2(acc[c][1][0], acc[c][1][1]);
        const unsigned pa3 = pack_h2(acc[c][1][2], acc[c][1][3]);
        unsigned bf[8][2];
#pragma unroll
        for (int jp = 0; jp < 4; jp++)
            ldmx4(bf[jp * 2][0], bf[jp * 2][1],
                  bf[jp * 2 + 1][0], bf[jp * 2 + 1][1],
                  Vs + (st * 64 + jp * 16 + brow8) * 136 + wc * 16 + bcol8);
#pragma unroll
        for (int j = 0; j < 8; j++)
            mma_f16(oacc[j], pa0, pa1, pa2, pa3, bf[j][0], bf[j][1]);
        if (c + 1 < 8) { sts_v((c + 1) & 1); __syncthreads(); }
    }

    // ---------------- Phase 5: cross-warp (wc) reduction ----------------
    // redO layout: [area][j][lane] float4, conflict-free.
    __syncthreads();    // PV reads of Vs done; redO overlays Vs
    if (wc >= 4) {
        const int area = wr * 4 + (wc - 4);
#pragma unroll
        for (int j = 0; j < 8; j++) {
            float4 v = {oacc[j][0], oacc[j][1], oacc[j][2], oacc[j][3]};
            redO[(area * 8 + j) * 32 + l] = v;
        }
    }
    __syncthreads();
    if (wc < 4) {
        const int area = wr * 4 + wc;
#pragma unroll
        for (int j = 0; j < 8; j++) {
            float4 v = redO[(area * 8 + j) * 32 + l];
            oacc[j][0] += v.x; oacc[j][1] += v.y;
            oacc[j][2] += v.z; oacc[j][3] += v.w;
        }
    }
    __syncthreads();
    if (wc >= 2 && wc < 4) {
        const int area = wr * 2 + (wc - 2);
#pragma unroll
        for (int j = 0; j < 8; j++) {
            float4 v = {oacc[j][0], oacc[j][1], oacc[j][2], oacc[j][3]};
            redO[(area * 8 + j) * 32 + l] = v;
        }
    }
    __syncthreads();
    if (wc < 2) {
        const int area = wr * 2 + wc;
#pragma unroll
        for (int j = 0; j < 8; j++) {
            float4 v = redO[(area * 8 + j) * 32 + l];
            oacc[j][0] += v.x; oacc[j][1] += v.y;
            oacc[j][2] += v.z; oacc[j][3] += v.w;
        }
    }
    __syncthreads();
    if (wc == 1) {
#pragma unroll
        for (int j = 0; j < 8; j++) {
            float4 v = {oacc[j][0], oacc[j][1], oacc[j][2], oacc[j][3]};
            redO[(wr * 8 + j) * 32 + l] = v;
        }
    }
    __syncthreads();
    if (wc == 0) {
#pragma unroll
        for (int j = 0; j < 8; j++) {
            float4 v = redO[(wr * 8 + j) * 32 + l];
            oacc[j][0] += v.x; oacc[j][1] += v.y;
            oacc[j][2] += v.z; oacc[j][3] += v.w;
        }
        // ---------------- write ctx (fp16) ----------------
        const int r0 = n0 + wr * 16 + g;
#pragma unroll
        for (int j = 0; j < 8; j++) {
            const int col = h * DD + j * 8 + 2 * t;
            *reinterpret_cast<unsigned*>(
                &ctxh[((size_t)b * NN + r0) * CC + col]) =
                pack_h2(oacc[j][0], oacc[j][1]);
            *reinterpret_cast<unsigned*>(
                &ctxh[((size_t)b * NN + r0 + 8) * CC + col]) =
                pack_h2(oacc[j][2], oacc[j][3]);
        }
    }
}

// ---------------------------------------------------------------------------
extern "C" void kernel_launch(void* const* d_in, const int* in_sizes, int n_in,
                              void* d_out, int out_size)
{
    (void)in_sizes; (void)n_in; (void)out_size;
    const float* x      = (const float*)d_in[0];
    const float* w_qkv  = (const float*)d_in[1];
    const float* b_qkv  = (const float*)d_in[2];
    const float* w_proj = (const float*)d_in[3];
    const float* b_proj = (const float*)d_in[4];

    float* out  = (float*)d_out;
    float* attn = out + (size_t)BB * NN * CC;

    __half *xh, *qkvh, *ctxh, *wqkvT, *wprojT, *vt;
    cudaGetSymbolAddress((void**)&xh, g_xh);
    cudaGetSymbolAddress((void**)&qkvh, g_qkvh);
    cudaGetSymbolAddress((void**)&ctxh, g_ctxh);
    cudaGetSymbolAddress((void**)&wqkvT, g_wqkvT);
    cudaGetSymbolAddress((void**)&wprojT, g_wprojT);
    cudaGetSymbolAddress((void**)&vt, g_vt);

    const int g_smem = 6 * 10240;                     // 61440
    const int a_smem = (32 * 72 + 3 * 128 * 72) * 2;  // 59904
    cudaFuncSetAttribute(gemm_h3,
        cudaFuncAttributeMaxDynamicSharedMemorySize, g_smem);
    cudaFuncSetAttribute(attn_fused_h,
        cudaFuncAttributeMaxDynamicSharedMemorySize, a_smem);

    // 0) One-time conversions
    const int nx8 = BB * NN * CC / 8;
    cvt_f32_h<<<(nx8 + 255) / 256, 256>>>(x, xh, nx8);
    transpose_w_h<<<dim3(CC / 32, 3 * CC / 32), dim3(32, 8)>>>(
        w_qkv, wqkvT, CC, 3 * CC);
    transpose_w_h<<<dim3(CC / 32, CC / 32), dim3(32, 8)>>>(
        w_proj, wprojT, CC, CC);

    // 1) QKV projection (fp16 out)
    gemm_h3<<<dim3(3 * CC / 128, BB * NN / 128), 256, g_smem>>>(
        xh, wqkvT, b_qkv, qkvh, BB * NN, 3 * CC, CC, 1);

    // 1b) V transpose -> [bh][d][m]
    transpose_v_h<<<dim3(NN / 128, BB * HH), 256>>>(qkvh, vt);

    // 2) Fully fused attention: QK^T + softmax + attn write + PV + ctx write
    attn_fused_h<<<dim3(NN / FROWS, BB * HH), 512, a_smem>>>(
        qkvh, vt, attn, ctxh);

    // 3) Output projection (fp32 out)
    gemm_h3<<<dim3(CC / 128, BB * NN / 128), 256, g_smem>>>(
        ctxh, wprojT, b_proj, out, BB * NN, CC, CC, 0);
}